// round 8
// baseline (speedup 1.0000x reference)
#include <cuda_runtime.h>

typedef unsigned long long ull;

#define Bb 256
#define Tt 512
#define Vv 30000
#define Ee 256

// ---------------- static device scratch ----------------
__device__ float g_embedW[(size_t)Vv * 192];       // [V][192] fwd 0..95, bwd 96..191 (bih folded, r/z pre-halved)
__device__ float g_x1[(size_t)Bb * Tt * 64];       // layer0 outputs [B][T][64]
__device__ float g_gi1[(size_t)Bb * Tt * 192];     // layer1 input gates (r/z pre-halved)
__device__ float g_top[Bb * 64];
__device__ int   g_len[Bb];

// ---------------- fast math ----------------
__device__ __forceinline__ float fast_tanh(float x) {
    float y; asm("tanh.approx.f32 %0, %1;" : "=f"(y) : "f"(x));
    return y;
}
__device__ __forceinline__ void fma2(ull& d, ull a, ull b) {
    asm("fma.rn.f32x2 %0, %1, %2, %0;" : "+l"(d) : "l"(a), "l"(b));
}
__device__ __forceinline__ ull add2(ull a, ull b) {
    ull r; asm("add.rn.f32x2 %0, %1, %2;" : "=l"(r) : "l"(a), "l"(b));
    return r;
}
__device__ __forceinline__ ull dup2(float v) {
    ull r; asm("mov.b64 %0, {%1, %1};" : "=l"(r) : "f"(v));
    return r;
}
__device__ __forceinline__ ull pack2(float lo, float hi) {
    ull r; asm("mov.b64 %0, {%1, %2};" : "=l"(r) : "f"(lo), "f"(hi));
    return r;
}
__device__ __forceinline__ float hsum2(ull v) {
    unsigned lo, hi;
    asm("mov.b64 {%0, %1}, %2;" : "=r"(lo), "=r"(hi) : "l"(v));
    return __uint_as_float(lo) + __uint_as_float(hi);
}

// ---------------- lengths from attention mask (prefix mask) ----------------
__global__ void lens_kernel(const int* __restrict__ mask)
{
    int w = (blockIdx.x * blockDim.x + threadIdx.x) >> 5;
    int lane = threadIdx.x & 31;
    if (w >= Bb) return;
    int s = 0;
    for (int i = lane; i < Tt; i += 32) s += mask[w * Tt + i];
#pragma unroll
    for (int off = 16; off; off >>= 1) s += __shfl_xor_sync(0xffffffffu, s, off);
    if (lane == 0) g_len[w] = s;
}

// ---------------- fused GEMM: C[M,192] = (A[M,K] @ [Wf;Wb]^T + bias) * colscale ----------------
// BM=64, BN=192, BK=16, 256 threads, single-buffer smem, 3 CTAs/SM.  (R6 proven config)
__global__ __launch_bounds__(256, 3)
void gemm192_kernel(const float* __restrict__ A,
                    const float* __restrict__ Wf, const float* __restrict__ Wb,
                    const float* __restrict__ bf, const float* __restrict__ bb_,
                    float* __restrict__ C, int M, int K,
                    const int* __restrict__ rowmask)
{
    __shared__ float As[16][68];
    __shared__ float Bs[16][196];

    int m0 = blockIdx.x * 64;
    if (rowmask && rowmask[m0] == 0) return;   // prefix mask: whole 64-row block padded

    int tid = threadIdx.x;
    int tx = tid & 31;        // cols tx + 32*j, j=0..5
    int ty = tid >> 5;        // rows ty*8 .. ty*8+7
    int lkk = tid & 15;
    int lrow = tid >> 4;

    const float* abase = A + (m0 + lrow) * K + lkk;
    const float* wfb = Wf + lrow * K + lkk;
    const float* wbb = Wb + lrow * K + lkk;
    bool arow_ok[4];
#pragma unroll
    for (int p = 0; p < 4; p++) arow_ok[p] = (m0 + lrow + 16 * p) < M;
    int K16 = K * 16;

    ull acc[4][6];
#pragma unroll
    for (int i = 0; i < 4; i++)
#pragma unroll
        for (int j = 0; j < 6; j++) acc[i][j] = 0ull;

    for (int k0 = 0; k0 < K; k0 += 16) {
#pragma unroll
        for (int p = 0; p < 4; p++)
            As[lkk][lrow + 16 * p] = arow_ok[p] ? abase[p * K16 + k0] : 0.f;
#pragma unroll
        for (int p = 0; p < 6; p++)
            Bs[lkk][lrow + 16 * p] = wfb[p * K16 + k0];
#pragma unroll
        for (int p = 6; p < 12; p++)
            Bs[lkk][lrow + 16 * p] = wbb[(p - 6) * K16 + k0];
        __syncthreads();
#pragma unroll
        for (int k = 0; k < 16; k++) {
            ulonglong2 q0 = *(const ulonglong2*)&As[k][ty * 8];
            ulonglong2 q1 = *(const ulonglong2*)&As[k][ty * 8 + 4];
            ull a2[4] = { q0.x, q0.y, q1.x, q1.y };
            ull b2[6];
#pragma unroll
            for (int j = 0; j < 6; j++) b2[j] = dup2(Bs[k][tx + 32 * j]);
#pragma unroll
            for (int i = 0; i < 4; i++)
#pragma unroll
                for (int j = 0; j < 6; j++)
                    fma2(acc[i][j], a2[i], b2[j]);
        }
        __syncthreads();
    }

#pragma unroll
    for (int j = 0; j < 6; j++) {
        int n = tx + 32 * j;
        // j: 0=r_f 1=z_f 2=n_f 3=r_b 4=z_b 5=n_b ; r/z pre-halved for tanh-form sigmoid
        float scale = (j == 2 || j == 5) ? 1.0f : 0.5f;
        float bias = (j < 3) ? bf[n] : bb_[n - 96];
#pragma unroll
        for (int i = 0; i < 4; i++) {
            int gm0 = m0 + ty * 8 + 2 * i;
            unsigned lo, hi;
            asm("mov.b64 {%0, %1}, %2;" : "=r"(lo), "=r"(hi) : "l"(acc[i][j]));
            if (gm0 < M)     C[(size_t)gm0 * 192 + n]       = (__uint_as_float(lo) + bias) * scale;
            if (gm0 + 1 < M) C[(size_t)(gm0 + 1) * 192 + n] = (__uint_as_float(hi) + bias) * scale;
        }
    }
}

// ---------------- GRU recurrence: warp = (batch pair, dir); 2 streams share Whh ----------------
template<bool L0>
__global__ __launch_bounds__(128)
void gru_kernel(const float* __restrict__ gi,
                const int* __restrict__ ids,
                const float* __restrict__ Whh_f, const float* __restrict__ bhh_f,
                const float* __restrict__ Whh_b, const float* __restrict__ bhh_b)
{
    __shared__ float sh[4][2][64];        // [warp][parity][stream*32+lane]
    __shared__ int   sid[4][2][Tt];       // L0 only (ids pre-zeroed at padded positions)

    int wib = threadIdx.x >> 5;
    int lane = threadIdx.x & 31;
    int w = blockIdx.x * 4 + wib;         // w in [0, 256)
    int dir  = w & 1;
    int pr_  = w >> 1;                    // pair id [0,128)
    int b0 = 2 * pr_;

    const float* Whh = dir ? Whh_b : Whh_f;
    const float* bhh = dir ? bhh_b : bhh_f;

    // Whh rows packed as f32x2 pairs; r/z rows pre-halved (tanh-form sigmoid)
    ull Wr2[16], Wz2[16], Wn2[16];
#pragma unroll
    for (int q = 0; q < 8; q++) {
        float4 v;
        v = *(const float4*)&Whh[lane * 32 + q * 4];
        Wr2[2*q]   = pack2(0.5f * v.x, 0.5f * v.y);
        Wr2[2*q+1] = pack2(0.5f * v.z, 0.5f * v.w);
        v = *(const float4*)&Whh[(32 + lane) * 32 + q * 4];
        Wz2[2*q]   = pack2(0.5f * v.x, 0.5f * v.y);
        Wz2[2*q+1] = pack2(0.5f * v.z, 0.5f * v.w);
        v = *(const float4*)&Whh[(64 + lane) * 32 + q * 4];
        Wn2[2*q]   = pack2(v.x, v.y);
        Wn2[2*q+1] = pack2(v.z, v.w);
    }
    ull bR = pack2(0.5f * bhh[lane], 0.f);
    ull bZ = pack2(0.5f * bhh[32 + lane], 0.f);
    ull bN = pack2(bhh[64 + lane], 0.f);

    int lens[2] = { g_len[b0], g_len[b0 + 1] };
    int len = max(lens[0], lens[1]);
    int tstep = dir ? -1 : 1;

    if (L0) {
#pragma unroll
        for (int st = 0; st < 2; st++) {
            const int* idrow = ids + (b0 + st) * Tt;
            for (int i = lane; i < Tt; i += 32) sid[wib][st][i] = idrow[i];
        }
        __syncwarp();
    }

    int tc[2];
    const float* gbase[2];
#pragma unroll
    for (int st = 0; st < 2; st++) {
        tc[st] = dir ? (lens[st] - 1) : 0;
        gbase[st] = L0 ? (gi + dir * 96)
                       : (gi + (size_t)(b0 + st) * Tt * 192 + dir * 96);
    }

    // gi row pointer for stream st at (clamped) time t
    auto gip = [&](int st, int t) -> const float* {
        t = min(max(t, 0), Tt - 1);
        if (L0) return gbase[st] + (size_t)sid[wib][st][t] * 192;
        else    return gbase[st] + (size_t)t * 192;
    };

    // distance-3 prefetch pipelines
    float p0r[2], p0z[2], p0n[2], p1r[2], p1z[2], p1n[2], p2r[2], p2z[2], p2n[2];
#pragma unroll
    for (int st = 0; st < 2; st++) {
        const float* p;
        p = gip(st, tc[st]);
        p0r[st] = __ldg(p + lane); p0z[st] = __ldg(p + 32 + lane); p0n[st] = __ldg(p + 64 + lane);
        p = gip(st, tc[st] + tstep);
        p1r[st] = __ldg(p + lane); p1z[st] = __ldg(p + 32 + lane); p1n[st] = __ldg(p + 64 + lane);
        p = gip(st, tc[st] + 2 * tstep);
        p2r[st] = __ldg(p + lane); p2z[st] = __ldg(p + 32 + lane); p2n[st] = __ldg(p + 64 + lane);
    }

    float h[2] = { 0.f, 0.f };
    float* outp[2];
#pragma unroll
    for (int st = 0; st < 2; st++)
        outp[st] = L0 ? (g_x1 + ((size_t)(b0 + st) * Tt + tc[st]) * 64 + dir * 32 + lane) : nullptr;
    int outstep = tstep * 64;

    for (int s = 0; s < len; s++) {
        float cr[2], cz[2], cn[2];
#pragma unroll
        for (int st = 0; st < 2; st++) {
            cr[st] = p0r[st]; cz[st] = p0z[st]; cn[st] = p0n[st];
            p0r[st] = p1r[st]; p0z[st] = p1z[st]; p0n[st] = p1n[st];
            p1r[st] = p2r[st]; p1z[st] = p2z[st]; p1n[st] = p2n[st];
            const float* p = gip(st, tc[st] + 3 * tstep);
            p2r[st] = __ldg(p + lane); p2z[st] = __ldg(p + 32 + lane); p2n[st] = __ldg(p + 64 + lane);
        }

        int par = s & 1;
        sh[wib][par][lane]      = h[0];
        sh[wib][par][32 + lane] = h[1];
        __syncwarp();

        ull ra[2], rb[2], za[2], zb[2], na[2], nb2[2];
#pragma unroll
        for (int st = 0; st < 2; st++) {
            ull h2[16];
#pragma unroll
            for (int i = 0; i < 8; i++) {
                ulonglong2 q2 = *(const ulonglong2*)&sh[wib][par][st * 32 + 4 * i];
                h2[2 * i] = q2.x; h2[2 * i + 1] = q2.y;
            }
            ra[st] = bR; rb[st] = 0ull; za[st] = bZ; zb[st] = 0ull; na[st] = bN; nb2[st] = 0ull;
#pragma unroll
            for (int k = 0; k < 16; k += 2) {
                fma2(na[st],  Wn2[k],     h2[k]);
                fma2(nb2[st], Wn2[k + 1], h2[k + 1]);
                fma2(ra[st],  Wr2[k],     h2[k]);
                fma2(rb[st],  Wr2[k + 1], h2[k + 1]);
                fma2(za[st],  Wz2[k],     h2[k]);
                fma2(zb[st],  Wz2[k + 1], h2[k + 1]);
            }
        }

#pragma unroll
        for (int st = 0; st < 2; st++) {
            float ar = hsum2(add2(ra[st], rb[st]));
            float az = hsum2(add2(za[st], zb[st]));
            float an = hsum2(add2(na[st], nb2[st]));
            // sigmoid(x) = 0.5 + 0.5*tanh(x/2); r/z args pre-halved upstream
            float r = fmaf(0.5f, fast_tanh(cr[st] + ar), 0.5f);
            float z = fmaf(0.5f, fast_tanh(cz[st] + az), 0.5f);
            float n = fast_tanh(fmaf(r, an, cn[st]));
            float hnew = fmaf(z, h[st] - n, n);
            bool active = s < lens[st];
            h[st] = active ? hnew : h[st];
            if (L0 && active) *outp[st] = h[st];
            outp[st] += outstep;
            tc[st] += tstep;
        }
    }
    if (!L0) {
        g_top[b0 * 64 + dir * 32 + lane]       = h[0];
        g_top[(b0 + 1) * 64 + dir * 32 + lane] = h[1];
    }
}

// ---------------- final linear [B,64] @ [6,64]^T + bias ----------------
__global__ void out_kernel(const float* __restrict__ Wout, const float* __restrict__ bout,
                           float* __restrict__ out)
{
    int w = (blockIdx.x * blockDim.x + threadIdx.x) >> 5;
    int lane = threadIdx.x & 31;
    if (w >= Bb) return;
    float t0 = g_top[w * 64 + lane];
    float t1 = g_top[w * 64 + 32 + lane];
#pragma unroll
    for (int o = 0; o < 6; o++) {
        float s = t0 * Wout[o * 64 + lane] + t1 * Wout[o * 64 + 32 + lane];
#pragma unroll
        for (int off = 16; off; off >>= 1) s += __shfl_xor_sync(0xffffffffu, s, off);
        if (lane == 0) out[w * 6 + o] = s + bout[o];
    }
}

// ---------------- launch ----------------
extern "C" void kernel_launch(void* const* d_in, const int* in_sizes, int n_in,
                              void* d_out, int out_size)
{
    const int*   ids     = (const int*)d_in[0];
    const int*   mask    = (const int*)d_in[1];
    const float* embed   = (const float*)d_in[2];
    const float* Wih_l0f = (const float*)d_in[3];
    const float* Whh_l0f = (const float*)d_in[4];
    const float* bih_l0f = (const float*)d_in[5];
    const float* bhh_l0f = (const float*)d_in[6];
    const float* Wih_l0b = (const float*)d_in[7];
    const float* Whh_l0b = (const float*)d_in[8];
    const float* bih_l0b = (const float*)d_in[9];
    const float* bhh_l0b = (const float*)d_in[10];
    const float* Wih_l1f = (const float*)d_in[11];
    const float* Whh_l1f = (const float*)d_in[12];
    const float* bih_l1f = (const float*)d_in[13];
    const float* bhh_l1f = (const float*)d_in[14];
    const float* Wih_l1b = (const float*)d_in[15];
    const float* Whh_l1b = (const float*)d_in[16];
    const float* bih_l1b = (const float*)d_in[17];
    const float* bhh_l1b = (const float*)d_in[18];
    const float* Wout    = (const float*)d_in[19];
    const float* bout    = (const float*)d_in[20];
    float* out = (float*)d_out;

    float *p_embedW = nullptr, *p_x1 = nullptr, *p_gi1 = nullptr;
    cudaGetSymbolAddress((void**)&p_embedW, g_embedW);
    cudaGetSymbolAddress((void**)&p_x1, g_x1);
    cudaGetSymbolAddress((void**)&p_gi1, g_gi1);

    // 1) lengths
    lens_kernel<<<8, 1024>>>(mask);
    // 2) embedW = (embed @ [Wih_l0f;Wih_l0b]^T + bias) * colscale
    gemm192_kernel<<<(Vv + 63) / 64, 256>>>(embed, Wih_l0f, Wih_l0b, bih_l0f, bih_l0b,
                                            p_embedW, Vv, Ee, nullptr);
    // 3) layer-0 bidirectional recurrence -> x1  (2 streams/warp, 256 warps)
    gru_kernel<true><<<64, 128>>>(p_embedW, ids, Whh_l0f, bhh_l0f, Whh_l0b, bhh_l0b);
    // 4) gi1 = (x1 @ [Wih_l1f;Wih_l1b]^T + bias) * colscale  (masked blocks skipped)
    gemm192_kernel<<<(Bb * Tt) / 64, 256>>>(p_x1, Wih_l1f, Wih_l1b, bih_l1f, bih_l1b,
                                            p_gi1, Bb * Tt, 64, mask);
    // 5) layer-1 recurrence -> final hiddens
    gru_kernel<false><<<64, 128>>>(p_gi1, nullptr, Whh_l1f, bhh_l1f, Whh_l1b, bhh_l1b);
    // 6) output projection
    out_kernel<<<8, 1024>>>(Wout, bout, out);
}

// round 9
// speedup vs baseline: 1.3529x; 1.3529x over previous
#include <cuda_runtime.h>

typedef unsigned long long ull;

#define Bb 256
#define Tt 512
#define Vv 30000
#define Ee 256

// ---------------- static device scratch ----------------
__device__ float g_embedW[(size_t)Vv * 192];       // [V][192] fwd 0..95, bwd 96..191 (bih folded, r/z pre-halved)
__device__ float g_x1[(size_t)Bb * Tt * 64];       // layer0 outputs [B][T][64]
__device__ float g_gi1[(size_t)Bb * Tt * 192];     // layer1 input gates (r/z pre-halved)
__device__ float g_top[Bb * 64];
__device__ int   g_len[Bb];

// ---------------- fast math ----------------
__device__ __forceinline__ float fast_tanh(float x) {
    float y; asm("tanh.approx.f32 %0, %1;" : "=f"(y) : "f"(x));
    return y;
}
__device__ __forceinline__ void fma2(ull& d, ull a, ull b) {
    asm("fma.rn.f32x2 %0, %1, %2, %0;" : "+l"(d) : "l"(a), "l"(b));
}
__device__ __forceinline__ ull add2(ull a, ull b) {
    ull r; asm("add.rn.f32x2 %0, %1, %2;" : "=l"(r) : "l"(a), "l"(b));
    return r;
}
__device__ __forceinline__ ull dup2(float v) {
    ull r; asm("mov.b64 %0, {%1, %1};" : "=l"(r) : "f"(v));
    return r;
}
__device__ __forceinline__ ull pack2(float lo, float hi) {
    ull r; asm("mov.b64 %0, {%1, %2};" : "=l"(r) : "f"(lo), "f"(hi));
    return r;
}
__device__ __forceinline__ float hsum2(ull v) {
    unsigned lo, hi;
    asm("mov.b64 {%0, %1}, %2;" : "=r"(lo), "=r"(hi) : "l"(v));
    return __uint_as_float(lo) + __uint_as_float(hi);
}

// ---------------- lengths from attention mask (prefix mask) ----------------
__global__ void lens_kernel(const int* __restrict__ mask)
{
    int w = (blockIdx.x * blockDim.x + threadIdx.x) >> 5;
    int lane = threadIdx.x & 31;
    if (w >= Bb) return;
    int s = 0;
    for (int i = lane; i < Tt; i += 32) s += mask[w * Tt + i];
#pragma unroll
    for (int off = 16; off; off >>= 1) s += __shfl_xor_sync(0xffffffffu, s, off);
    if (lane == 0) g_len[w] = s;
}

// ---------------- fused GEMM: C[M,192] = (A[M,K] @ [Wf;Wb]^T + bias) * colscale ----------------
// BM=64, BN=192, BK=16, 256 threads, single-buffer smem, 3 CTAs/SM.  (R6 proven config)
__global__ __launch_bounds__(256, 3)
void gemm192_kernel(const float* __restrict__ A,
                    const float* __restrict__ Wf, const float* __restrict__ Wb,
                    const float* __restrict__ bf, const float* __restrict__ bb_,
                    float* __restrict__ C, int M, int K,
                    const int* __restrict__ rowmask)
{
    __shared__ float As[16][68];
    __shared__ float Bs[16][196];

    int m0 = blockIdx.x * 64;
    if (rowmask && rowmask[m0] == 0) return;   // prefix mask: whole 64-row block padded

    int tid = threadIdx.x;
    int tx = tid & 31;        // cols tx + 32*j, j=0..5
    int ty = tid >> 5;        // rows ty*8 .. ty*8+7
    int lkk = tid & 15;
    int lrow = tid >> 4;

    const float* abase = A + (m0 + lrow) * K + lkk;
    const float* wfb = Wf + lrow * K + lkk;
    const float* wbb = Wb + lrow * K + lkk;
    bool arow_ok[4];
#pragma unroll
    for (int p = 0; p < 4; p++) arow_ok[p] = (m0 + lrow + 16 * p) < M;
    int K16 = K * 16;

    ull acc[4][6];
#pragma unroll
    for (int i = 0; i < 4; i++)
#pragma unroll
        for (int j = 0; j < 6; j++) acc[i][j] = 0ull;

    for (int k0 = 0; k0 < K; k0 += 16) {
#pragma unroll
        for (int p = 0; p < 4; p++)
            As[lkk][lrow + 16 * p] = arow_ok[p] ? abase[p * K16 + k0] : 0.f;
#pragma unroll
        for (int p = 0; p < 6; p++)
            Bs[lkk][lrow + 16 * p] = wfb[p * K16 + k0];
#pragma unroll
        for (int p = 6; p < 12; p++)
            Bs[lkk][lrow + 16 * p] = wbb[(p - 6) * K16 + k0];
        __syncthreads();
#pragma unroll
        for (int k = 0; k < 16; k++) {
            ulonglong2 q0 = *(const ulonglong2*)&As[k][ty * 8];
            ulonglong2 q1 = *(const ulonglong2*)&As[k][ty * 8 + 4];
            ull a2[4] = { q0.x, q0.y, q1.x, q1.y };
            ull b2[6];
#pragma unroll
            for (int j = 0; j < 6; j++) b2[j] = dup2(Bs[k][tx + 32 * j]);
#pragma unroll
            for (int i = 0; i < 4; i++)
#pragma unroll
                for (int j = 0; j < 6; j++)
                    fma2(acc[i][j], a2[i], b2[j]);
        }
        __syncthreads();
    }

#pragma unroll
    for (int j = 0; j < 6; j++) {
        int n = tx + 32 * j;
        // j: 0=r_f 1=z_f 2=n_f 3=r_b 4=z_b 5=n_b ; r/z pre-halved for tanh-form sigmoid
        float scale = (j == 2 || j == 5) ? 1.0f : 0.5f;
        float bias = (j < 3) ? bf[n] : bb_[n - 96];
#pragma unroll
        for (int i = 0; i < 4; i++) {
            int gm0 = m0 + ty * 8 + 2 * i;
            unsigned lo, hi;
            asm("mov.b64 {%0, %1}, %2;" : "=r"(lo), "=r"(hi) : "l"(acc[i][j]));
            if (gm0 < M)     C[(size_t)gm0 * 192 + n]       = (__uint_as_float(lo) + bias) * scale;
            if (gm0 + 1 < M) C[(size_t)(gm0 + 1) * 192 + n] = (__uint_as_float(hi) + bias) * scale;
        }
    }
}

// ---------------- GRU recurrence: warp = (batch pair, dir); 2 streams share Whh ----------------
// Register-economized: matvec in two k-halves (peak h2 = 8 ull), full 255-reg budget.
template<bool L0>
__global__ __launch_bounds__(128, 1)
void gru_kernel(const float* __restrict__ gi,
                const int* __restrict__ ids,
                const float* __restrict__ Whh_f, const float* __restrict__ bhh_f,
                const float* __restrict__ Whh_b, const float* __restrict__ bhh_b)
{
    __shared__ float sh[4][2][64];        // [warp][parity][stream*32+lane]
    __shared__ int   sid[4][2][Tt];       // L0 only (ids are zero at padded positions)

    int wib = threadIdx.x >> 5;
    int lane = threadIdx.x & 31;
    int w = blockIdx.x * 4 + wib;         // [0, 256)
    int dir = w & 1;
    int b0  = (w >> 1) * 2;

    const float* Whh = dir ? Whh_b : Whh_f;
    const float* bhh = dir ? bhh_b : bhh_f;

    // Whh rows packed as f32x2 pairs; r/z rows pre-halved (tanh-form sigmoid)
    ull Wr2[16], Wz2[16], Wn2[16];
#pragma unroll
    for (int q = 0; q < 8; q++) {
        float4 v;
        v = *(const float4*)&Whh[lane * 32 + q * 4];
        Wr2[2*q]   = pack2(0.5f * v.x, 0.5f * v.y);
        Wr2[2*q+1] = pack2(0.5f * v.z, 0.5f * v.w);
        v = *(const float4*)&Whh[(32 + lane) * 32 + q * 4];
        Wz2[2*q]   = pack2(0.5f * v.x, 0.5f * v.y);
        Wz2[2*q+1] = pack2(0.5f * v.z, 0.5f * v.w);
        v = *(const float4*)&Whh[(64 + lane) * 32 + q * 4];
        Wn2[2*q]   = pack2(v.x, v.y);
        Wn2[2*q+1] = pack2(v.z, v.w);
    }
    float br = 0.5f * bhh[lane];
    float bz = 0.5f * bhh[32 + lane];
    float bn = bhh[64 + lane];

    int len0 = g_len[b0], len1 = g_len[b0 + 1];
    int len = max(len0, len1);
    int tstep = dir ? -1 : 1;

    if (L0) {
        const int* idrow0 = ids + b0 * Tt;
        const int* idrow1 = ids + (b0 + 1) * Tt;
        for (int i = lane; i < Tt; i += 32) {
            sid[wib][0][i] = idrow0[i];
            sid[wib][1][i] = idrow1[i];
        }
        __syncwarp();
    }

    int tc0 = dir ? (len0 - 1) : 0;
    int tc1 = dir ? (len1 - 1) : 0;
    const float* gb0 = L0 ? (gi + dir * 96) : (gi + (size_t)b0 * Tt * 192 + dir * 96);
    const float* gb1 = L0 ? (gi + dir * 96) : (gi + (size_t)(b0 + 1) * Tt * 192 + dir * 96);

    auto gip0 = [&](int t) -> const float* {
        t = min(max(t, 0), Tt - 1);
        return L0 ? (gb0 + (size_t)sid[wib][0][t] * 192) : (gb0 + (size_t)t * 192);
    };
    auto gip1 = [&](int t) -> const float* {
        t = min(max(t, 0), Tt - 1);
        return L0 ? (gb1 + (size_t)sid[wib][1][t] * 192) : (gb1 + (size_t)t * 192);
    };

    // distance-3 prefetch pipelines (scalars, not arrays)
    const float* p;
    p = gip0(tc0);              float a0r = __ldg(p + lane), a0z = __ldg(p + 32 + lane), a0n = __ldg(p + 64 + lane);
    p = gip0(tc0 + tstep);      float a1r = __ldg(p + lane), a1z = __ldg(p + 32 + lane), a1n = __ldg(p + 64 + lane);
    p = gip0(tc0 + 2 * tstep);  float a2r = __ldg(p + lane), a2z = __ldg(p + 32 + lane), a2n = __ldg(p + 64 + lane);
    p = gip1(tc1);              float e0r = __ldg(p + lane), e0z = __ldg(p + 32 + lane), e0n = __ldg(p + 64 + lane);
    p = gip1(tc1 + tstep);      float e1r = __ldg(p + lane), e1z = __ldg(p + 32 + lane), e1n = __ldg(p + 64 + lane);
    p = gip1(tc1 + 2 * tstep);  float e2r = __ldg(p + lane), e2z = __ldg(p + 32 + lane), e2n = __ldg(p + 64 + lane);

    float h0 = 0.f, h1 = 0.f;
    float* outp0 = L0 ? (g_x1 + ((size_t)b0 * Tt + tc0) * 64 + dir * 32 + lane) : nullptr;
    float* outp1 = L0 ? (g_x1 + ((size_t)(b0 + 1) * Tt + tc1) * 64 + dir * 32 + lane) : nullptr;
    int outstep = tstep * 64;

    for (int s = 0; s < len; s++) {
        float c0r = a0r, c0z = a0z, c0n = a0n;
        float c1r = e0r, c1z = e0z, c1n = e0n;
        a0r = a1r; a0z = a1z; a0n = a1n;
        a1r = a2r; a1z = a2z; a1n = a2n;
        e0r = e1r; e0z = e1z; e0n = e1n;
        e1r = e2r; e1z = e2z; e1n = e2n;
        p = gip0(tc0 + 3 * tstep);
        a2r = __ldg(p + lane); a2z = __ldg(p + 32 + lane); a2n = __ldg(p + 64 + lane);
        p = gip1(tc1 + 3 * tstep);
        e2r = __ldg(p + lane); e2z = __ldg(p + 32 + lane); e2n = __ldg(p + 64 + lane);

        int par = s & 1;
        sh[wib][par][lane]      = h0;
        sh[wib][par][32 + lane] = h1;
        __syncwarp();

        // stream 0 matvec, two k-halves (peak 8 ull of h live)
        ull ra0 = 0ull, za0 = 0ull, na0 = 0ull, rb0 = 0ull, zb0 = 0ull, nb0 = 0ull;
#pragma unroll
        for (int half = 0; half < 2; half++) {
            ull h2[8];
#pragma unroll
            for (int i = 0; i < 4; i++) {
                ulonglong2 q2 = *(const ulonglong2*)&sh[wib][par][half * 16 + 4 * i];
                h2[2 * i] = q2.x; h2[2 * i + 1] = q2.y;
            }
#pragma unroll
            for (int k = 0; k < 8; k += 2) {
                int kw = half * 8 + k;
                fma2(na0, Wn2[kw],     h2[k]);
                fma2(nb0, Wn2[kw + 1], h2[k + 1]);
                fma2(ra0, Wr2[kw],     h2[k]);
                fma2(rb0, Wr2[kw + 1], h2[k + 1]);
                fma2(za0, Wz2[kw],     h2[k]);
                fma2(zb0, Wz2[kw + 1], h2[k + 1]);
            }
        }
        // stream 1 matvec
        ull ra1 = 0ull, za1 = 0ull, na1 = 0ull, rb1 = 0ull, zb1 = 0ull, nb1 = 0ull;
#pragma unroll
        for (int half = 0; half < 2; half++) {
            ull h2[8];
#pragma unroll
            for (int i = 0; i < 4; i++) {
                ulonglong2 q2 = *(const ulonglong2*)&sh[wib][par][32 + half * 16 + 4 * i];
                h2[2 * i] = q2.x; h2[2 * i + 1] = q2.y;
            }
#pragma unroll
            for (int k = 0; k < 8; k += 2) {
                int kw = half * 8 + k;
                fma2(na1, Wn2[kw],     h2[k]);
                fma2(nb1, Wn2[kw + 1], h2[k + 1]);
                fma2(ra1, Wr2[kw],     h2[k]);
                fma2(rb1, Wr2[kw + 1], h2[k + 1]);
                fma2(za1, Wz2[kw],     h2[k]);
                fma2(zb1, Wz2[kw + 1], h2[k + 1]);
            }
        }

        // activations (independent chains; ptxas overlaps stream0's MUFUs with stream1's tail)
        float r0 = fmaf(0.5f, fast_tanh(c0r + br + hsum2(add2(ra0, rb0))), 0.5f);
        float z0 = fmaf(0.5f, fast_tanh(c0z + bz + hsum2(add2(za0, zb0))), 0.5f);
        float n0 = fast_tanh(fmaf(r0, bn + hsum2(add2(na0, nb0)), c0n));
        float r1 = fmaf(0.5f, fast_tanh(c1r + br + hsum2(add2(ra1, rb1))), 0.5f);
        float z1 = fmaf(0.5f, fast_tanh(c1z + bz + hsum2(add2(za1, zb1))), 0.5f);
        float n1 = fast_tanh(fmaf(r1, bn + hsum2(add2(na1, nb1)), c1n));

        float hn0 = fmaf(z0, h0 - n0, n0);
        float hn1 = fmaf(z1, h1 - n1, n1);
        bool act0 = s < len0, act1 = s < len1;
        h0 = act0 ? hn0 : h0;
        h1 = act1 ? hn1 : h1;

        if (L0) {
            if (act0) *outp0 = h0;
            if (act1) *outp1 = h1;
            outp0 += outstep; outp1 += outstep;
        }
        tc0 += tstep; tc1 += tstep;
    }
    if (!L0) {
        g_top[b0 * 64 + dir * 32 + lane]       = h0;
        g_top[(b0 + 1) * 64 + dir * 32 + lane] = h1;
    }
}

// ---------------- final linear [B,64] @ [6,64]^T + bias ----------------
__global__ void out_kernel(const float* __restrict__ Wout, const float* __restrict__ bout,
                           float* __restrict__ out)
{
    int w = (blockIdx.x * blockDim.x + threadIdx.x) >> 5;
    int lane = threadIdx.x & 31;
    if (w >= Bb) return;
    float t0 = g_top[w * 64 + lane];
    float t1 = g_top[w * 64 + 32 + lane];
#pragma unroll
    for (int o = 0; o < 6; o++) {
        float s = t0 * Wout[o * 64 + lane] + t1 * Wout[o * 64 + 32 + lane];
#pragma unroll
        for (int off = 16; off; off >>= 1) s += __shfl_xor_sync(0xffffffffu, s, off);
        if (lane == 0) out[w * 6 + o] = s + bout[o];
    }
}

// ---------------- launch ----------------
extern "C" void kernel_launch(void* const* d_in, const int* in_sizes, int n_in,
                              void* d_out, int out_size)
{
    const int*   ids     = (const int*)d_in[0];
    const int*   mask    = (const int*)d_in[1];
    const float* embed   = (const float*)d_in[2];
    const float* Wih_l0f = (const float*)d_in[3];
    const float* Whh_l0f = (const float*)d_in[4];
    const float* bih_l0f = (const float*)d_in[5];
    const float* bhh_l0f = (const float*)d_in[6];
    const float* Wih_l0b = (const float*)d_in[7];
    const float* Whh_l0b = (const float*)d_in[8];
    const float* bih_l0b = (const float*)d_in[9];
    const float* bhh_l0b = (const float*)d_in[10];
    const float* Wih_l1f = (const float*)d_in[11];
    const float* Whh_l1f = (const float*)d_in[12];
    const float* bih_l1f = (const float*)d_in[13];
    const float* bhh_l1f = (const float*)d_in[14];
    const float* Wih_l1b = (const float*)d_in[15];
    const float* Whh_l1b = (const float*)d_in[16];
    const float* bih_l1b = (const float*)d_in[17];
    const float* bhh_l1b = (const float*)d_in[18];
    const float* Wout    = (const float*)d_in[19];
    const float* bout    = (const float*)d_in[20];
    float* out = (float*)d_out;

    float *p_embedW = nullptr, *p_x1 = nullptr, *p_gi1 = nullptr;
    cudaGetSymbolAddress((void**)&p_embedW, g_embedW);
    cudaGetSymbolAddress((void**)&p_x1, g_x1);
    cudaGetSymbolAddress((void**)&p_gi1, g_gi1);

    // 1) lengths
    lens_kernel<<<8, 1024>>>(mask);
    // 2) embedW = (embed @ [Wih_l0f;Wih_l0b]^T + bias) * colscale
    gemm192_kernel<<<(Vv + 63) / 64, 256>>>(embed, Wih_l0f, Wih_l0b, bih_l0f, bih_l0b,
                                            p_embedW, Vv, Ee, nullptr);
    // 3) layer-0 bidirectional recurrence -> x1  (2 streams/warp, 256 warps)
    gru_kernel<true><<<64, 128>>>(p_embedW, ids, Whh_l0f, bhh_l0f, Whh_l0b, bhh_l0b);
    // 4) gi1 = (x1 @ [Wih_l1f;Wih_l1b]^T + bias) * colscale  (masked blocks skipped)
    gemm192_kernel<<<(Bb * Tt) / 64, 256>>>(p_x1, Wih_l1f, Wih_l1b, bih_l1f, bih_l1b,
                                            p_gi1, Bb * Tt, 64, mask);
    // 5) layer-1 recurrence -> final hiddens
    gru_kernel<false><<<64, 128>>>(p_gi1, nullptr, Whh_l1f, bhh_l1f, Whh_l1b, bhh_l1b);
    // 6) output projection
    out_kernel<<<8, 1024>>>(Wout, bout, out);
}

// round 10
// speedup vs baseline: 1.8863x; 1.3943x over previous
#include <cuda_runtime.h>

typedef unsigned long long ull;

#define Bb 256
#define Tt 512
#define Vv 30000
#define Ee 256

// ---------------- static device scratch ----------------
__device__ float g_embedW[(size_t)Vv * 192];       // [V][192] fwd 0..95, bwd 96..191 (bih folded, r/z pre-halved)
__device__ float g_x1[(size_t)Bb * Tt * 64];       // layer0 outputs [B][T][64]
__device__ float g_gi1[(size_t)Bb * Tt * 192];     // layer1 input gates (r/z pre-halved)
__device__ float g_top[Bb * 64];
__device__ int   g_len[Bb];

// ---------------- fast math ----------------
__device__ __forceinline__ float fast_tanh(float x) {
    float y; asm("tanh.approx.f32 %0, %1;" : "=f"(y) : "f"(x));
    return y;
}
__device__ __forceinline__ void fma2(ull& d, ull a, ull b) {
    asm("fma.rn.f32x2 %0, %1, %2, %0;" : "+l"(d) : "l"(a), "l"(b));
}
__device__ __forceinline__ ull add2(ull a, ull b) {
    ull r; asm("add.rn.f32x2 %0, %1, %2;" : "=l"(r) : "l"(a), "l"(b));
    return r;
}
__device__ __forceinline__ ull dup2(float v) {
    ull r; asm("mov.b64 %0, {%1, %1};" : "=l"(r) : "f"(v));
    return r;
}
__device__ __forceinline__ ull pack2(float lo, float hi) {
    ull r; asm("mov.b64 %0, {%1, %2};" : "=l"(r) : "f"(lo), "f"(hi));
    return r;
}
__device__ __forceinline__ float hsum2(ull v) {
    unsigned lo, hi;
    asm("mov.b64 {%0, %1}, %2;" : "=r"(lo), "=r"(hi) : "l"(v));
    return __uint_as_float(lo) + __uint_as_float(hi);
}

// ---------------- lengths from attention mask (prefix mask) ----------------
__global__ void lens_kernel(const int* __restrict__ mask)
{
    int w = (blockIdx.x * blockDim.x + threadIdx.x) >> 5;
    int lane = threadIdx.x & 31;
    if (w >= Bb) return;
    int s = 0;
    for (int i = lane; i < Tt; i += 32) s += mask[w * Tt + i];
#pragma unroll
    for (int off = 16; off; off >>= 1) s += __shfl_xor_sync(0xffffffffu, s, off);
    if (lane == 0) g_len[w] = s;
}

// ---------------- fused GEMM: C[M,192] = (A[M,K] @ [Wf;Wb]^T + bias) * colscale ----------------
// BM=64, BN=192, BK=16, 256 threads, single-buffer smem, 3 CTAs/SM.  (R6 proven config)
__global__ __launch_bounds__(256, 3)
void gemm192_kernel(const float* __restrict__ A,
                    const float* __restrict__ Wf, const float* __restrict__ Wb,
                    const float* __restrict__ bf, const float* __restrict__ bb_,
                    float* __restrict__ C, int M, int K,
                    const int* __restrict__ rowmask)
{
    __shared__ float As[16][68];
    __shared__ float Bs[16][196];

    int m0 = blockIdx.x * 64;
    if (rowmask && rowmask[m0] == 0) return;   // prefix mask: whole 64-row block padded

    int tid = threadIdx.x;
    int tx = tid & 31;        // cols tx + 32*j, j=0..5
    int ty = tid >> 5;        // rows ty*8 .. ty*8+7
    int lkk = tid & 15;
    int lrow = tid >> 4;

    const float* abase = A + (m0 + lrow) * K + lkk;
    const float* wfb = Wf + lrow * K + lkk;
    const float* wbb = Wb + lrow * K + lkk;
    bool arow_ok[4];
#pragma unroll
    for (int p = 0; p < 4; p++) arow_ok[p] = (m0 + lrow + 16 * p) < M;
    int K16 = K * 16;

    ull acc[4][6];
#pragma unroll
    for (int i = 0; i < 4; i++)
#pragma unroll
        for (int j = 0; j < 6; j++) acc[i][j] = 0ull;

    for (int k0 = 0; k0 < K; k0 += 16) {
#pragma unroll
        for (int p = 0; p < 4; p++)
            As[lkk][lrow + 16 * p] = arow_ok[p] ? abase[p * K16 + k0] : 0.f;
#pragma unroll
        for (int p = 0; p < 6; p++)
            Bs[lkk][lrow + 16 * p] = wfb[p * K16 + k0];
#pragma unroll
        for (int p = 6; p < 12; p++)
            Bs[lkk][lrow + 16 * p] = wbb[(p - 6) * K16 + k0];
        __syncthreads();
#pragma unroll
        for (int k = 0; k < 16; k++) {
            ulonglong2 q0 = *(const ulonglong2*)&As[k][ty * 8];
            ulonglong2 q1 = *(const ulonglong2*)&As[k][ty * 8 + 4];
            ull a2[4] = { q0.x, q0.y, q1.x, q1.y };
            ull b2[6];
#pragma unroll
            for (int j = 0; j < 6; j++) b2[j] = dup2(Bs[k][tx + 32 * j]);
#pragma unroll
            for (int i = 0; i < 4; i++)
#pragma unroll
                for (int j = 0; j < 6; j++)
                    fma2(acc[i][j], a2[i], b2[j]);
        }
        __syncthreads();
    }

#pragma unroll
    for (int j = 0; j < 6; j++) {
        int n = tx + 32 * j;
        // j: 0=r_f 1=z_f 2=n_f 3=r_b 4=z_b 5=n_b ; r/z pre-halved for tanh-form sigmoid
        float scale = (j == 2 || j == 5) ? 1.0f : 0.5f;
        float bias = (j < 3) ? bf[n] : bb_[n - 96];
#pragma unroll
        for (int i = 0; i < 4; i++) {
            int gm0 = m0 + ty * 8 + 2 * i;
            unsigned lo, hi;
            asm("mov.b64 {%0, %1}, %2;" : "=r"(lo), "=r"(hi) : "l"(acc[i][j]));
            if (gm0 < M)     C[(size_t)gm0 * 192 + n]       = (__uint_as_float(lo) + bias) * scale;
            if (gm0 + 1 < M) C[(size_t)(gm0 + 1) * 192 + n] = (__uint_as_float(hi) + bias) * scale;
        }
    }
}

// ---------------- GRU recurrence: warp = (batch, dir); 8 warps/CTA -> 2 warps/SMSP ----------------
// Per-warp body identical to the proven R6 kernel; only the CTA shape changed so two
// independent recurrence warps co-reside per scheduler and hide each other's latency.
template<bool L0>
__global__ __launch_bounds__(256, 1)
void gru_kernel(const float* __restrict__ gi,
                const int* __restrict__ ids,
                const float* __restrict__ Whh_f, const float* __restrict__ bhh_f,
                const float* __restrict__ Whh_b, const float* __restrict__ bhh_b)
{
    __shared__ float sh[8][2][32];        // [warp][parity][lane]
    __shared__ int   sid[8][Tt];          // L0 only

    int wib = threadIdx.x >> 5;           // 0..7
    int lane = threadIdx.x & 31;
    int w = blockIdx.x * 8 + wib;         // [0, 512)
    int dir = w & 1;
    int b   = w >> 1;
    const float* Whh = dir ? Whh_b : Whh_f;
    const float* bhh = dir ? bhh_b : bhh_f;

    // Whh rows packed as f32x2 pairs; r/z rows pre-halved (tanh-form sigmoid)
    ull Wr2[16], Wz2[16], Wn2[16];
#pragma unroll
    for (int q = 0; q < 8; q++) {
        float4 v;
        v = *(const float4*)&Whh[lane * 32 + q * 4];
        Wr2[2*q]   = pack2(0.5f * v.x, 0.5f * v.y);
        Wr2[2*q+1] = pack2(0.5f * v.z, 0.5f * v.w);
        v = *(const float4*)&Whh[(32 + lane) * 32 + q * 4];
        Wz2[2*q]   = pack2(0.5f * v.x, 0.5f * v.y);
        Wz2[2*q+1] = pack2(0.5f * v.z, 0.5f * v.w);
        v = *(const float4*)&Whh[(64 + lane) * 32 + q * 4];
        Wn2[2*q]   = pack2(v.x, v.y);
        Wn2[2*q+1] = pack2(v.z, v.w);
    }
    ull bR = pack2(0.5f * bhh[lane], 0.f);
    ull bZ = pack2(0.5f * bhh[32 + lane], 0.f);
    ull bN = pack2(bhh[64 + lane], 0.f);

    int len = g_len[b];
    int lenm1 = len - 1;

    if (L0) {
        const int* idrow = ids + b * Tt;
        for (int i = lane; i < len; i += 32) sid[wib][i] = idrow[i];
        __syncwarp();
    }

    int tstep = dir ? -1 : 1;
    int tcur  = dir ? lenm1 : 0;

    // direction-adjusted base pointers
    const float* gi0  = gi + dir * 96;                              // L0: + sid[t]*192
    const float* gib  = gi + (size_t)b * Tt * 192 + dir * 96;       // L1: + t*192

    // clamped time index, branch-free
    auto tclamp = [&](int t) { return min(max(t, 0), lenm1); };
    auto gip = [&](int t) -> const float* {
        if (L0) return gi0 + (size_t)sid[wib][t] * 192;
        else    return gib + (size_t)t * 192;
    };

    // distance-3 prefetch pipeline (clamped -> no init branches)
    const float* p;
    p = gip(tclamp(tcur));
    float p0r = __ldg(p + lane), p0z = __ldg(p + 32 + lane), p0n = __ldg(p + 64 + lane);
    p = gip(tclamp(tcur + tstep));
    float p1r = __ldg(p + lane), p1z = __ldg(p + 32 + lane), p1n = __ldg(p + 64 + lane);
    p = gip(tclamp(tcur + 2 * tstep));
    float p2r = __ldg(p + lane), p2z = __ldg(p + 32 + lane), p2n = __ldg(p + 64 + lane);

    float h = 0.f;
    float* outp = L0 ? (g_x1 + ((size_t)b * Tt + tcur) * 64 + dir * 32 + lane) : nullptr;
    int outstep = tstep * 64;

#pragma unroll 2
    for (int s = 0; s < len; s++) {
        float cr = p0r, cz = p0z, cn = p0n;
        p0r = p1r; p0z = p1z; p0n = p1n;
        p1r = p2r; p1z = p2z; p1n = p2n;
        // branch-free clamped prefetch (redundant tail loads are harmless)
        p = gip(tclamp(tcur + 3 * tstep));
        p2r = __ldg(p + lane); p2z = __ldg(p + 32 + lane); p2n = __ldg(p + 64 + lane);

        int par = s & 1;
        sh[wib][par][lane] = h;
        __syncwarp();
        ull h2[16];
#pragma unroll
        for (int i = 0; i < 8; i++) {
            ulonglong2 q2 = *(const ulonglong2*)&sh[wib][par][4 * i];
            h2[2 * i] = q2.x; h2[2 * i + 1] = q2.y;
        }

        ull ra = bR, rb = 0ull, za = bZ, zb = 0ull, na = bN, nb2 = 0ull;
#pragma unroll
        for (int k = 0; k < 16; k += 2) {
            fma2(na,  Wn2[k],     h2[k]);
            fma2(nb2, Wn2[k + 1], h2[k + 1]);
            fma2(ra,  Wr2[k],     h2[k]);
            fma2(rb,  Wr2[k + 1], h2[k + 1]);
            fma2(za,  Wz2[k],     h2[k]);
            fma2(zb,  Wz2[k + 1], h2[k + 1]);
        }
        float ar = hsum2(add2(ra, rb));
        float az = hsum2(add2(za, zb));
        float an = hsum2(add2(na, nb2));

        // sigmoid(x) = 0.5 + 0.5*tanh(x/2); r/z args pre-halved upstream
        float r = fmaf(0.5f, fast_tanh(cr + ar), 0.5f);
        float z = fmaf(0.5f, fast_tanh(cz + az), 0.5f);
        float n = fast_tanh(fmaf(r, an, cn));
        h = fmaf(z, h - n, n);

        if (L0) { *outp = h; outp += outstep; }
        tcur += tstep;
    }
    if (!L0)
        g_top[b * 64 + dir * 32 + lane] = h;
}

// ---------------- final linear [B,64] @ [6,64]^T + bias ----------------
__global__ void out_kernel(const float* __restrict__ Wout, const float* __restrict__ bout,
                           float* __restrict__ out)
{
    int w = (blockIdx.x * blockDim.x + threadIdx.x) >> 5;
    int lane = threadIdx.x & 31;
    if (w >= Bb) return;
    float t0 = g_top[w * 64 + lane];
    float t1 = g_top[w * 64 + 32 + lane];
#pragma unroll
    for (int o = 0; o < 6; o++) {
        float s = t0 * Wout[o * 64 + lane] + t1 * Wout[o * 64 + 32 + lane];
#pragma unroll
        for (int off = 16; off; off >>= 1) s += __shfl_xor_sync(0xffffffffu, s, off);
        if (lane == 0) out[w * 6 + o] = s + bout[o];
    }
}

// ---------------- launch ----------------
extern "C" void kernel_launch(void* const* d_in, const int* in_sizes, int n_in,
                              void* d_out, int out_size)
{
    const int*   ids     = (const int*)d_in[0];
    const int*   mask    = (const int*)d_in[1];
    const float* embed   = (const float*)d_in[2];
    const float* Wih_l0f = (const float*)d_in[3];
    const float* Whh_l0f = (const float*)d_in[4];
    const float* bih_l0f = (const float*)d_in[5];
    const float* bhh_l0f = (const float*)d_in[6];
    const float* Wih_l0b = (const float*)d_in[7];
    const float* Whh_l0b = (const float*)d_in[8];
    const float* bih_l0b = (const float*)d_in[9];
    const float* bhh_l0b = (const float*)d_in[10];
    const float* Wih_l1f = (const float*)d_in[11];
    const float* Whh_l1f = (const float*)d_in[12];
    const float* bih_l1f = (const float*)d_in[13];
    const float* bhh_l1f = (const float*)d_in[14];
    const float* Wih_l1b = (const float*)d_in[15];
    const float* Whh_l1b = (const float*)d_in[16];
    const float* bih_l1b = (const float*)d_in[17];
    const float* bhh_l1b = (const float*)d_in[18];
    const float* Wout    = (const float*)d_in[19];
    const float* bout    = (const float*)d_in[20];
    float* out = (float*)d_out;

    float *p_embedW = nullptr, *p_x1 = nullptr, *p_gi1 = nullptr;
    cudaGetSymbolAddress((void**)&p_embedW, g_embedW);
    cudaGetSymbolAddress((void**)&p_x1, g_x1);
    cudaGetSymbolAddress((void**)&p_gi1, g_gi1);

    // 1) lengths
    lens_kernel<<<8, 1024>>>(mask);
    // 2) embedW = (embed @ [Wih_l0f;Wih_l0b]^T + bias) * colscale
    gemm192_kernel<<<(Vv + 63) / 64, 256>>>(embed, Wih_l0f, Wih_l0b, bih_l0f, bih_l0b,
                                            p_embedW, Vv, Ee, nullptr);
    // 3) layer-0 bidirectional recurrence -> x1  (64 CTAs x 8 warps -> 2 warps/SMSP)
    gru_kernel<true><<<64, 256>>>(p_embedW, ids, Whh_l0f, bhh_l0f, Whh_l0b, bhh_l0b);
    // 4) gi1 = (x1 @ [Wih_l1f;Wih_l1b]^T + bias) * colscale  (masked blocks skipped)
    gemm192_kernel<<<(Bb * Tt) / 64, 256>>>(p_x1, Wih_l1f, Wih_l1b, bih_l1f, bih_l1b,
                                            p_gi1, Bb * Tt, 64, mask);
    // 5) layer-1 recurrence -> final hiddens
    gru_kernel<false><<<64, 256>>>(p_gi1, nullptr, Whh_l1f, bhh_l1f, Whh_l1b, bhh_l1b);
    // 6) output projection
    out_kernel<<<8, 1024>>>(Wout, bout, out);
}

// round 11
// speedup vs baseline: 2.0701x; 1.0974x over previous
#include <cuda_runtime.h>

typedef unsigned long long ull;

#define Bb 256
#define Tt 512
#define Vv 30000
#define Ee 256

// ---------------- static device scratch ----------------
__device__ float g_embedW[(size_t)Vv * 192];       // [V][192] fwd 0..95, bwd 96..191 (bih folded, r/z pre-halved)
__device__ float g_x1[(size_t)Bb * Tt * 64];       // layer0 outputs [B][T][64]
__device__ float g_gi1[(size_t)Bb * Tt * 192];     // layer1 input gates (r/z pre-halved)
__device__ float g_top[Bb * 64];
__device__ int   g_len[Bb];

// ---------------- fast math ----------------
__device__ __forceinline__ float fast_tanh(float x) {
    float y; asm("tanh.approx.f32 %0, %1;" : "=f"(y) : "f"(x));
    return y;
}
__device__ __forceinline__ void fma2(ull& d, ull a, ull b) {
    asm("fma.rn.f32x2 %0, %1, %2, %0;" : "+l"(d) : "l"(a), "l"(b));
}
__device__ __forceinline__ ull add2(ull a, ull b) {
    ull r; asm("add.rn.f32x2 %0, %1, %2;" : "=l"(r) : "l"(a), "l"(b));
    return r;
}
__device__ __forceinline__ ull dup2(float v) {
    ull r; asm("mov.b64 %0, {%1, %1};" : "=l"(r) : "f"(v));
    return r;
}
__device__ __forceinline__ ull pack2(float lo, float hi) {
    ull r; asm("mov.b64 %0, {%1, %2};" : "=l"(r) : "f"(lo), "f"(hi));
    return r;
}
__device__ __forceinline__ float hsum2(ull v) {
    unsigned lo, hi;
    asm("mov.b64 {%0, %1}, %2;" : "=r"(lo), "=r"(hi) : "l"(v));
    return __uint_as_float(lo) + __uint_as_float(hi);
}
__device__ __forceinline__ void cp_async4(unsigned smem_addr, const float* gptr) {
    asm volatile("cp.async.ca.shared.global [%0], [%1], 4;" :: "r"(smem_addr), "l"(gptr));
}

// ---------------- lengths from attention mask (prefix mask) ----------------
__global__ void lens_kernel(const int* __restrict__ mask)
{
    int w = (blockIdx.x * blockDim.x + threadIdx.x) >> 5;
    int lane = threadIdx.x & 31;
    if (w >= Bb) return;
    int s = 0;
    for (int i = lane; i < Tt; i += 32) s += mask[w * Tt + i];
#pragma unroll
    for (int off = 16; off; off >>= 1) s += __shfl_xor_sync(0xffffffffu, s, off);
    if (lane == 0) g_len[w] = s;
}

// ---------------- fused GEMM: C[M,192] = (A[M,K] @ [Wf;Wb]^T + bias) * colscale ----------------
// BM=64, BN=192, BK=16, 256 threads; 3-stage cp.async pipeline, one syncthreads/tile.
#define ASZ (16 * 68)
#define BSZ (16 * 196)
#define STAGE_F (ASZ + BSZ)
#define GEMM_SMEM_BYTES (3 * STAGE_F * 4)

__global__ __launch_bounds__(256)
void gemm192_kernel(const float* __restrict__ A,
                    const float* __restrict__ Wf, const float* __restrict__ Wb,
                    const float* __restrict__ bf, const float* __restrict__ bb_,
                    float* __restrict__ C, int M, int K,
                    const int* __restrict__ rowmask)
{
    extern __shared__ float smem[];   // [3][ASZ | BSZ]

    int m0 = blockIdx.x * 64;
    if (rowmask && rowmask[m0] == 0) return;   // prefix mask: whole 64-row block padded

    int tid = threadIdx.x;
    int tx = tid & 31;        // cols tx + 32*j, j=0..5
    int ty = tid >> 5;        // rows ty*8 .. ty*8+7
    int lkk = tid & 15;
    int lrow = tid >> 4;

    // A gmem row offsets (clamped into range; stores are guarded)
    size_t aoff[4];
#pragma unroll
    for (int p = 0; p < 4; p++) {
        int gm = m0 + lrow + 16 * p;
        if (gm > M - 1) gm = M - 1;
        aoff[p] = (size_t)gm * K + lkk;
    }
    const float* wfb = Wf + lrow * K + lkk;
    const float* wbb = Wb + lrow * K + lkk;
    int K16 = K * 16;

    unsigned sbase = (unsigned)__cvta_generic_to_shared(smem);
    unsigned sa_off = (unsigned)((lkk * 68 + lrow) * 4);
    unsigned sb_off = (unsigned)((ASZ + lkk * 196 + lrow) * 4);

    auto load_tile = [&](int stg, int k0) {
        unsigned sg = sbase + (unsigned)(stg * STAGE_F * 4);
#pragma unroll
        for (int p = 0; p < 4; p++)
            cp_async4(sg + sa_off + 16 * p * 4, A + aoff[p] + k0);
#pragma unroll
        for (int p = 0; p < 6; p++)
            cp_async4(sg + sb_off + 16 * p * 4, wfb + p * K16 + k0);
#pragma unroll
        for (int p = 6; p < 12; p++)
            cp_async4(sg + sb_off + 16 * p * 4, wbb + (p - 6) * K16 + k0);
        asm volatile("cp.async.commit_group;");
    };

    ull acc[4][6];
#pragma unroll
    for (int i = 0; i < 4; i++)
#pragma unroll
        for (int j = 0; j < 6; j++) acc[i][j] = 0ull;

    int nk = K >> 4;   // K is 256 or 64 -> nk >= 4
    load_tile(0, 0);
    load_tile(1, 16);

    int stg = 0;
    for (int it = 0; it < nk; ++it) {
        asm volatile("cp.async.wait_group 1;");   // tile `it` resident
        __syncthreads();

        const float* As_ = smem + stg * STAGE_F;
        const float* Bs_ = As_ + ASZ;
#pragma unroll
        for (int k = 0; k < 16; k++) {
            ulonglong2 q0 = *(const ulonglong2*)&As_[k * 68 + ty * 8];
            ulonglong2 q1 = *(const ulonglong2*)&As_[k * 68 + ty * 8 + 4];
            ull a2[4] = { q0.x, q0.y, q1.x, q1.y };
            ull b2[6];
#pragma unroll
            for (int j = 0; j < 6; j++) b2[j] = dup2(Bs_[k * 196 + tx + 32 * j]);
#pragma unroll
            for (int i = 0; i < 4; i++)
#pragma unroll
                for (int j = 0; j < 6; j++)
                    fma2(acc[i][j], a2[i], b2[j]);
        }

        // issue tile it+2 into the stage freed at iter it-1 (all warps past sync(it))
        if (it + 2 < nk) {
            int ns = stg + 2; if (ns >= 3) ns -= 3;
            load_tile(ns, (it + 2) * 16);
        } else {
            asm volatile("cp.async.commit_group;");   // empty group keeps wait_group math exact
        }
        if (++stg == 3) stg = 0;
    }

#pragma unroll
    for (int j = 0; j < 6; j++) {
        int n = tx + 32 * j;
        // j: 0=r_f 1=z_f 2=n_f 3=r_b 4=z_b 5=n_b ; r/z pre-halved for tanh-form sigmoid
        float scale = (j == 2 || j == 5) ? 1.0f : 0.5f;
        float bias = (j < 3) ? bf[n] : bb_[n - 96];
#pragma unroll
        for (int i = 0; i < 4; i++) {
            int gm0 = m0 + ty * 8 + 2 * i;
            unsigned lo, hi;
            asm("mov.b64 {%0, %1}, %2;" : "=r"(lo), "=r"(hi) : "l"(acc[i][j]));
            if (gm0 < M)     C[(size_t)gm0 * 192 + n]       = (__uint_as_float(lo) + bias) * scale;
            if (gm0 + 1 < M) C[(size_t)(gm0 + 1) * 192 + n] = (__uint_as_float(hi) + bias) * scale;
        }
    }
}

// ---------------- GRU recurrence: warp = (batch, dir)  (R6 proven form) ----------------
template<bool L0>
__global__ __launch_bounds__(128)
void gru_kernel(const float* __restrict__ gi,
                const int* __restrict__ ids,
                const float* __restrict__ Whh_f, const float* __restrict__ bhh_f,
                const float* __restrict__ Whh_b, const float* __restrict__ bhh_b)
{
    __shared__ float sh[4][2][32];        // [warp][parity][lane]
    __shared__ int   sid[4][Tt];          // L0 only

    int wib = threadIdx.x >> 5;
    int lane = threadIdx.x & 31;
    int w = blockIdx.x * 4 + wib;
    int dir = w & 1;
    int b   = w >> 1;
    const float* Whh = dir ? Whh_b : Whh_f;
    const float* bhh = dir ? bhh_b : bhh_f;

    // Whh rows packed as f32x2 pairs; r/z rows pre-halved (tanh-form sigmoid)
    ull Wr2[16], Wz2[16], Wn2[16];
#pragma unroll
    for (int q = 0; q < 8; q++) {
        float4 v;
        v = *(const float4*)&Whh[lane * 32 + q * 4];
        Wr2[2*q]   = pack2(0.5f * v.x, 0.5f * v.y);
        Wr2[2*q+1] = pack2(0.5f * v.z, 0.5f * v.w);
        v = *(const float4*)&Whh[(32 + lane) * 32 + q * 4];
        Wz2[2*q]   = pack2(0.5f * v.x, 0.5f * v.y);
        Wz2[2*q+1] = pack2(0.5f * v.z, 0.5f * v.w);
        v = *(const float4*)&Whh[(64 + lane) * 32 + q * 4];
        Wn2[2*q]   = pack2(v.x, v.y);
        Wn2[2*q+1] = pack2(v.z, v.w);
    }
    ull bR = pack2(0.5f * bhh[lane], 0.f);
    ull bZ = pack2(0.5f * bhh[32 + lane], 0.f);
    ull bN = pack2(bhh[64 + lane], 0.f);

    int len = g_len[b];
    int lenm1 = len - 1;

    if (L0) {
        const int* idrow = ids + b * Tt;
        for (int i = lane; i < len; i += 32) sid[wib][i] = idrow[i];
        __syncwarp();
    }

    int tstep = dir ? -1 : 1;
    int tcur  = dir ? lenm1 : 0;

    // direction-adjusted base pointers
    const float* gi0  = gi + dir * 96;                              // L0: + sid[t]*192
    const float* gib  = gi + (size_t)b * Tt * 192 + dir * 96;       // L1: + t*192

    // clamped time index, branch-free
    auto tclamp = [&](int t) { return min(max(t, 0), lenm1); };
    auto gip = [&](int t) -> const float* {
        if (L0) return gi0 + (size_t)sid[wib][t] * 192;
        else    return gib + (size_t)t * 192;
    };

    // distance-3 prefetch pipeline (clamped -> no init branches)
    const float* p;
    p = gip(tclamp(tcur));
    float p0r = __ldg(p + lane), p0z = __ldg(p + 32 + lane), p0n = __ldg(p + 64 + lane);
    p = gip(tclamp(tcur + tstep));
    float p1r = __ldg(p + lane), p1z = __ldg(p + 32 + lane), p1n = __ldg(p + 64 + lane);
    p = gip(tclamp(tcur + 2 * tstep));
    float p2r = __ldg(p + lane), p2z = __ldg(p + 32 + lane), p2n = __ldg(p + 64 + lane);

    float h = 0.f;
    float* outp = L0 ? (g_x1 + ((size_t)b * Tt + tcur) * 64 + dir * 32 + lane) : nullptr;
    int outstep = tstep * 64;

#pragma unroll 2
    for (int s = 0; s < len; s++) {
        float cr = p0r, cz = p0z, cn = p0n;
        p0r = p1r; p0z = p1z; p0n = p1n;
        p1r = p2r; p1z = p2z; p1n = p2n;
        // branch-free clamped prefetch (redundant tail loads are harmless)
        p = gip(tclamp(tcur + 3 * tstep));
        p2r = __ldg(p + lane); p2z = __ldg(p + 32 + lane); p2n = __ldg(p + 64 + lane);

        int par = s & 1;
        sh[wib][par][lane] = h;
        __syncwarp();
        ull h2[16];
#pragma unroll
        for (int i = 0; i < 8; i++) {
            ulonglong2 q2 = *(const ulonglong2*)&sh[wib][par][4 * i];
            h2[2 * i] = q2.x; h2[2 * i + 1] = q2.y;
        }

        ull ra = bR, rb = 0ull, za = bZ, zb = 0ull, na = bN, nb2 = 0ull;
#pragma unroll
        for (int k = 0; k < 16; k += 2) {
            fma2(na,  Wn2[k],     h2[k]);
            fma2(nb2, Wn2[k + 1], h2[k + 1]);
            fma2(ra,  Wr2[k],     h2[k]);
            fma2(rb,  Wr2[k + 1], h2[k + 1]);
            fma2(za,  Wz2[k],     h2[k]);
            fma2(zb,  Wz2[k + 1], h2[k + 1]);
        }
        float ar = hsum2(add2(ra, rb));
        float az = hsum2(add2(za, zb));
        float an = hsum2(add2(na, nb2));

        // sigmoid(x) = 0.5 + 0.5*tanh(x/2); r/z args pre-halved upstream
        float r = fmaf(0.5f, fast_tanh(cr + ar), 0.5f);
        float z = fmaf(0.5f, fast_tanh(cz + az), 0.5f);
        float n = fast_tanh(fmaf(r, an, cn));
        h = fmaf(z, h - n, n);

        if (L0) { *outp = h; outp += outstep; }
        tcur += tstep;
    }
    if (!L0)
        g_top[b * 64 + dir * 32 + lane] = h;
}

// ---------------- final linear [B,64] @ [6,64]^T + bias ----------------
__global__ void out_kernel(const float* __restrict__ Wout, const float* __restrict__ bout,
                           float* __restrict__ out)
{
    int w = (blockIdx.x * blockDim.x + threadIdx.x) >> 5;
    int lane = threadIdx.x & 31;
    if (w >= Bb) return;
    float t0 = g_top[w * 64 + lane];
    float t1 = g_top[w * 64 + 32 + lane];
#pragma unroll
    for (int o = 0; o < 6; o++) {
        float s = t0 * Wout[o * 64 + lane] + t1 * Wout[o * 64 + 32 + lane];
#pragma unroll
        for (int off = 16; off; off >>= 1) s += __shfl_xor_sync(0xffffffffu, s, off);
        if (lane == 0) out[w * 6 + o] = s + bout[o];
    }
}

// ---------------- launch ----------------
extern "C" void kernel_launch(void* const* d_in, const int* in_sizes, int n_in,
                              void* d_out, int out_size)
{
    const int*   ids     = (const int*)d_in[0];
    const int*   mask    = (const int*)d_in[1];
    const float* embed   = (const float*)d_in[2];
    const float* Wih_l0f = (const float*)d_in[3];
    const float* Whh_l0f = (const float*)d_in[4];
    const float* bih_l0f = (const float*)d_in[5];
    const float* bhh_l0f = (const float*)d_in[6];
    const float* Wih_l0b = (const float*)d_in[7];
    const float* Whh_l0b = (const float*)d_in[8];
    const float* bih_l0b = (const float*)d_in[9];
    const float* bhh_l0b = (const float*)d_in[10];
    const float* Wih_l1f = (const float*)d_in[11];
    const float* Whh_l1f = (const float*)d_in[12];
    const float* bih_l1f = (const float*)d_in[13];
    const float* bhh_l1f = (const float*)d_in[14];
    const float* Wih_l1b = (const float*)d_in[15];
    const float* Whh_l1b = (const float*)d_in[16];
    const float* bih_l1b = (const float*)d_in[17];
    const float* bhh_l1b = (const float*)d_in[18];
    const float* Wout    = (const float*)d_in[19];
    const float* bout    = (const float*)d_in[20];
    float* out = (float*)d_out;

    float *p_embedW = nullptr, *p_x1 = nullptr, *p_gi1 = nullptr;
    cudaGetSymbolAddress((void**)&p_embedW, g_embedW);
    cudaGetSymbolAddress((void**)&p_x1, g_x1);
    cudaGetSymbolAddress((void**)&p_gi1, g_gi1);

    cudaFuncSetAttribute(gemm192_kernel, cudaFuncAttributeMaxDynamicSharedMemorySize, GEMM_SMEM_BYTES);

    // 1) lengths
    lens_kernel<<<8, 1024>>>(mask);
    // 2) embedW = (embed @ [Wih_l0f;Wih_l0b]^T + bias) * colscale
    gemm192_kernel<<<(Vv + 63) / 64, 256, GEMM_SMEM_BYTES>>>(embed, Wih_l0f, Wih_l0b, bih_l0f, bih_l0b,
                                                             p_embedW, Vv, Ee, nullptr);
    // 3) layer-0 bidirectional recurrence -> x1  (R6 shape: 128 CTAs x 4 warps)
    gru_kernel<true><<<128, 128>>>(p_embedW, ids, Whh_l0f, bhh_l0f, Whh_l0b, bhh_l0b);
    // 4) gi1 = (x1 @ [Wih_l1f;Wih_l1b]^T + bias) * colscale  (masked blocks skipped)
    gemm192_kernel<<<(Bb * Tt) / 64, 256, GEMM_SMEM_BYTES>>>(p_x1, Wih_l1f, Wih_l1b, bih_l1f, bih_l1b,
                                                             p_gi1, Bb * Tt, 64, mask);
    // 5) layer-1 recurrence -> final hiddens
    gru_kernel<false><<<128, 128>>>(p_gi1, nullptr, Whh_l1f, bhh_l1f, Whh_l1b, bhh_l1b);
    // 6) output projection
    out_kernel<<<8, 1024>>>(Wout, bout, out);
}

// round 12
// speedup vs baseline: 2.1710x; 1.0487x over previous
#include <cuda_runtime.h>

typedef unsigned long long ull;

#define Bb 256
#define Tt 512
#define Vv 30000
#define Ee 256

// ---------------- static device scratch ----------------
__device__ float g_embedW[(size_t)Vv * 192];       // [V][192] fwd 0..95, bwd 96..191 (bih folded, r/z pre-halved)
__device__ float g_x1[(size_t)Bb * Tt * 64];       // layer0 outputs [B][T][64]
__device__ float g_gi1[(size_t)Bb * Tt * 192];     // layer1 input gates (r/z pre-halved)

// ---------------- fast math ----------------
__device__ __forceinline__ float fast_tanh(float x) {
    float y; asm("tanh.approx.f32 %0, %1;" : "=f"(y) : "f"(x));
    return y;
}
__device__ __forceinline__ void fma2(ull& d, ull a, ull b) {
    asm("fma.rn.f32x2 %0, %1, %2, %0;" : "+l"(d) : "l"(a), "l"(b));
}
__device__ __forceinline__ ull add2(ull a, ull b) {
    ull r; asm("add.rn.f32x2 %0, %1, %2;" : "=l"(r) : "l"(a), "l"(b));
    return r;
}
__device__ __forceinline__ ull dup2(float v) {
    ull r; asm("mov.b64 %0, {%1, %1};" : "=l"(r) : "f"(v));
    return r;
}
__device__ __forceinline__ ull pack2(float lo, float hi) {
    ull r; asm("mov.b64 %0, {%1, %2};" : "=l"(r) : "f"(lo), "f"(hi));
    return r;
}
__device__ __forceinline__ float hsum2(ull v) {
    unsigned lo, hi;
    asm("mov.b64 {%0, %1}, %2;" : "=r"(lo), "=r"(hi) : "l"(v));
    return __uint_as_float(lo) + __uint_as_float(hi);
}

// ---------------- fused GEMM: C[M,192] = (A[M,K] @ [Wf;Wb]^T + bias) * colscale ----------------
// BM=64, BN=192, BK=16, 256 threads, single-buffer smem, 3 CTAs/SM.  (R6 proven config)
__global__ __launch_bounds__(256, 3)
void gemm192_kernel(const float* __restrict__ A,
                    const float* __restrict__ Wf, const float* __restrict__ Wb,
                    const float* __restrict__ bf, const float* __restrict__ bb_,
                    float* __restrict__ C, int M, int K,
                    const int* __restrict__ rowmask)
{
    __shared__ float As[16][68];
    __shared__ float Bs[16][196];

    int m0 = blockIdx.x * 64;
    if (rowmask && rowmask[m0] == 0) return;   // prefix mask: whole 64-row block padded

    int tid = threadIdx.x;
    int tx = tid & 31;        // cols tx + 32*j, j=0..5
    int ty = tid >> 5;        // rows ty*8 .. ty*8+7
    int lkk = tid & 15;
    int lrow = tid >> 4;

    const float* abase = A + (m0 + lrow) * K + lkk;
    const float* wfb = Wf + lrow * K + lkk;
    const float* wbb = Wb + lrow * K + lkk;
    bool arow_ok[4];
#pragma unroll
    for (int p = 0; p < 4; p++) arow_ok[p] = (m0 + lrow + 16 * p) < M;
    int K16 = K * 16;

    ull acc[4][6];
#pragma unroll
    for (int i = 0; i < 4; i++)
#pragma unroll
        for (int j = 0; j < 6; j++) acc[i][j] = 0ull;

    for (int k0 = 0; k0 < K; k0 += 16) {
#pragma unroll
        for (int p = 0; p < 4; p++)
            As[lkk][lrow + 16 * p] = arow_ok[p] ? abase[p * K16 + k0] : 0.f;
#pragma unroll
        for (int p = 0; p < 6; p++)
            Bs[lkk][lrow + 16 * p] = wfb[p * K16 + k0];
#pragma unroll
        for (int p = 6; p < 12; p++)
            Bs[lkk][lrow + 16 * p] = wbb[(p - 6) * K16 + k0];
        __syncthreads();
#pragma unroll
        for (int k = 0; k < 16; k++) {
            ulonglong2 q0 = *(const ulonglong2*)&As[k][ty * 8];
            ulonglong2 q1 = *(const ulonglong2*)&As[k][ty * 8 + 4];
            ull a2[4] = { q0.x, q0.y, q1.x, q1.y };
            ull b2[6];
#pragma unroll
            for (int j = 0; j < 6; j++) b2[j] = dup2(Bs[k][tx + 32 * j]);
#pragma unroll
            for (int i = 0; i < 4; i++)
#pragma unroll
                for (int j = 0; j < 6; j++)
                    fma2(acc[i][j], a2[i], b2[j]);
        }
        __syncthreads();
    }

#pragma unroll
    for (int j = 0; j < 6; j++) {
        int n = tx + 32 * j;
        // j: 0=r_f 1=z_f 2=n_f 3=r_b 4=z_b 5=n_b ; r/z pre-halved for tanh-form sigmoid
        float scale = (j == 2 || j == 5) ? 1.0f : 0.5f;
        float bias = (j < 3) ? bf[n] : bb_[n - 96];
#pragma unroll
        for (int i = 0; i < 4; i++) {
            int gm0 = m0 + ty * 8 + 2 * i;
            unsigned lo, hi;
            asm("mov.b64 {%0, %1}, %2;" : "=r"(lo), "=r"(hi) : "l"(acc[i][j]));
            if (gm0 < M)     C[(size_t)gm0 * 192 + n]       = (__uint_as_float(lo) + bias) * scale;
            if (gm0 + 1 < M) C[(size_t)(gm0 + 1) * 192 + n] = (__uint_as_float(hi) + bias) * scale;
        }
    }
}

// ---------------- GRU recurrence: warp = (batch, dir)  (R6 core, lens/out fused) ----------------
template<bool L0>
__global__ __launch_bounds__(128)
void gru_kernel(const float* __restrict__ gi,
                const int* __restrict__ ids,
                const int* __restrict__ mask,
                const float* __restrict__ Whh_f, const float* __restrict__ bhh_f,
                const float* __restrict__ Whh_b, const float* __restrict__ bhh_b,
                const float* __restrict__ Wout, const float* __restrict__ bout,
                float* __restrict__ out)
{
    __shared__ float sh[4][2][32];        // [warp][parity][lane]
    __shared__ int   sid[4][Tt];          // L0 only
    __shared__ float stop[2][64];         // L1 only: [pair-in-CTA][dir*32+lane]

    int wib = threadIdx.x >> 5;
    int lane = threadIdx.x & 31;
    int w = blockIdx.x * 4 + wib;
    int dir = w & 1;
    int b   = w >> 1;
    const float* Whh = dir ? Whh_b : Whh_f;
    const float* bhh = dir ? bhh_b : bhh_f;

    // Whh rows packed as f32x2 pairs; r/z rows pre-halved (tanh-form sigmoid)
    ull Wr2[16], Wz2[16], Wn2[16];
#pragma unroll
    for (int q = 0; q < 8; q++) {
        float4 v;
        v = *(const float4*)&Whh[lane * 32 + q * 4];
        Wr2[2*q]   = pack2(0.5f * v.x, 0.5f * v.y);
        Wr2[2*q+1] = pack2(0.5f * v.z, 0.5f * v.w);
        v = *(const float4*)&Whh[(32 + lane) * 32 + q * 4];
        Wz2[2*q]   = pack2(0.5f * v.x, 0.5f * v.y);
        Wz2[2*q+1] = pack2(0.5f * v.z, 0.5f * v.w);
        v = *(const float4*)&Whh[(64 + lane) * 32 + q * 4];
        Wn2[2*q]   = pack2(v.x, v.y);
        Wn2[2*q+1] = pack2(v.z, v.w);
    }
    ull bR = pack2(0.5f * bhh[lane], 0.f);
    ull bZ = pack2(0.5f * bhh[32 + lane], 0.f);
    ull bN = pack2(bhh[64 + lane], 0.f);

    // per-warp length from prefix mask (fused lens)
    int len = 0;
    {
        const int* mrow = mask + b * Tt;
#pragma unroll
        for (int i = 0; i < Tt / 32; i++) len += mrow[lane + 32 * i];
#pragma unroll
        for (int off = 16; off; off >>= 1) len += __shfl_xor_sync(0xffffffffu, len, off);
    }
    int lenm1 = len - 1;

    if (L0) {
        const int* idrow = ids + b * Tt;
        for (int i = lane; i < len; i += 32) sid[wib][i] = idrow[i];
        __syncwarp();
    }

    int tstep = dir ? -1 : 1;
    int tcur  = dir ? lenm1 : 0;

    // direction-adjusted base pointers
    const float* gi0  = gi + dir * 96;                              // L0: + sid[t]*192
    const float* gib  = gi + (size_t)b * Tt * 192 + dir * 96;       // L1: + t*192

    // clamped time index, branch-free
    auto tclamp = [&](int t) { return min(max(t, 0), lenm1); };
    auto gip = [&](int t) -> const float* {
        if (L0) return gi0 + (size_t)sid[wib][t] * 192;
        else    return gib + (size_t)t * 192;
    };

    // distance-3 prefetch pipeline (clamped -> no init branches)
    const float* p;
    p = gip(tclamp(tcur));
    float p0r = __ldg(p + lane), p0z = __ldg(p + 32 + lane), p0n = __ldg(p + 64 + lane);
    p = gip(tclamp(tcur + tstep));
    float p1r = __ldg(p + lane), p1z = __ldg(p + 32 + lane), p1n = __ldg(p + 64 + lane);
    p = gip(tclamp(tcur + 2 * tstep));
    float p2r = __ldg(p + lane), p2z = __ldg(p + 32 + lane), p2n = __ldg(p + 64 + lane);

    float h = 0.f;
    float* outp = L0 ? (g_x1 + ((size_t)b * Tt + tcur) * 64 + dir * 32 + lane) : nullptr;
    int outstep = tstep * 64;

#pragma unroll 6
    for (int s = 0; s < len; s++) {
        float cr = p0r, cz = p0z, cn = p0n;
        p0r = p1r; p0z = p1z; p0n = p1n;
        p1r = p2r; p1z = p2z; p1n = p2n;
        // branch-free clamped prefetch (redundant tail loads are harmless)
        p = gip(tclamp(tcur + 3 * tstep));
        p2r = __ldg(p + lane); p2z = __ldg(p + 32 + lane); p2n = __ldg(p + 64 + lane);

        int par = s & 1;
        sh[wib][par][lane] = h;
        __syncwarp();
        ull h2[16];
#pragma unroll
        for (int i = 0; i < 8; i++) {
            ulonglong2 q2 = *(const ulonglong2*)&sh[wib][par][4 * i];
            h2[2 * i] = q2.x; h2[2 * i + 1] = q2.y;
        }

        ull ra = bR, rb = 0ull, za = bZ, zb = 0ull, na = bN, nb2 = 0ull;
#pragma unroll
        for (int k = 0; k < 16; k += 2) {
            fma2(na,  Wn2[k],     h2[k]);
            fma2(nb2, Wn2[k + 1], h2[k + 1]);
            fma2(ra,  Wr2[k],     h2[k]);
            fma2(rb,  Wr2[k + 1], h2[k + 1]);
            fma2(za,  Wz2[k],     h2[k]);
            fma2(zb,  Wz2[k + 1], h2[k + 1]);
        }
        float ar = hsum2(add2(ra, rb));
        float az = hsum2(add2(za, zb));
        float an = hsum2(add2(na, nb2));

        // sigmoid(x) = 0.5 + 0.5*tanh(x/2); r/z args pre-halved upstream
        float r = fmaf(0.5f, fast_tanh(cr + ar), 0.5f);
        float z = fmaf(0.5f, fast_tanh(cz + az), 0.5f);
        float n = fast_tanh(fmaf(r, an, cn));
        h = fmaf(z, h - n, n);

        if (L0) { *outp = h; outp += outstep; }
        tcur += tstep;
    }

    if (!L0) {
        // fused output projection: warps (b,fwd) and (b,bwd) are CTA-adjacent
        int pi = wib >> 1;                       // batch pair index within CTA
        stop[pi][dir * 32 + lane] = h;
        __syncthreads();
        if (dir == 0) {
            float t0 = stop[pi][lane];
            float t1 = stop[pi][32 + lane];
#pragma unroll
            for (int o = 0; o < 6; o++) {
                float s2 = t0 * Wout[o * 64 + lane] + t1 * Wout[o * 64 + 32 + lane];
#pragma unroll
                for (int off = 16; off; off >>= 1) s2 += __shfl_xor_sync(0xffffffffu, s2, off);
                if (lane == 0) out[b * 6 + o] = s2 + bout[o];
            }
        }
    }
}

// ---------------- launch ----------------
extern "C" void kernel_launch(void* const* d_in, const int* in_sizes, int n_in,
                              void* d_out, int out_size)
{
    const int*   ids     = (const int*)d_in[0];
    const int*   mask    = (const int*)d_in[1];
    const float* embed   = (const float*)d_in[2];
    const float* Wih_l0f = (const float*)d_in[3];
    const float* Whh_l0f = (const float*)d_in[4];
    const float* bih_l0f = (const float*)d_in[5];
    const float* bhh_l0f = (const float*)d_in[6];
    const float* Wih_l0b = (const float*)d_in[7];
    const float* Whh_l0b = (const float*)d_in[8];
    const float* bih_l0b = (const float*)d_in[9];
    const float* bhh_l0b = (const float*)d_in[10];
    const float* Wih_l1f = (const float*)d_in[11];
    const float* Whh_l1f = (const float*)d_in[12];
    const float* bih_l1f = (const float*)d_in[13];
    const float* bhh_l1f = (const float*)d_in[14];
    const float* Wih_l1b = (const float*)d_in[15];
    const float* Whh_l1b = (const float*)d_in[16];
    const float* bih_l1b = (const float*)d_in[17];
    const float* bhh_l1b = (const float*)d_in[18];
    const float* Wout    = (const float*)d_in[19];
    const float* bout    = (const float*)d_in[20];
    float* out = (float*)d_out;

    float *p_embedW = nullptr, *p_x1 = nullptr, *p_gi1 = nullptr;
    cudaGetSymbolAddress((void**)&p_embedW, g_embedW);
    cudaGetSymbolAddress((void**)&p_x1, g_x1);
    cudaGetSymbolAddress((void**)&p_gi1, g_gi1);

    // 1) embedW = (embed @ [Wih_l0f;Wih_l0b]^T + bias) * colscale
    gemm192_kernel<<<(Vv + 63) / 64, 256>>>(embed, Wih_l0f, Wih_l0b, bih_l0f, bih_l0b,
                                            p_embedW, Vv, Ee, nullptr);
    // 2) layer-0 bidirectional recurrence -> x1  (lens fused per-warp)
    gru_kernel<true><<<128, 128>>>(p_embedW, ids, mask, Whh_l0f, bhh_l0f, Whh_l0b, bhh_l0b,
                                   nullptr, nullptr, nullptr);
    // 3) gi1 = (x1 @ [Wih_l1f;Wih_l1b]^T + bias) * colscale  (masked blocks skipped)
    gemm192_kernel<<<(Bb * Tt) / 64, 256>>>(p_x1, Wih_l1f, Wih_l1b, bih_l1f, bih_l1b,
                                            p_gi1, Bb * Tt, 64, mask);
    // 4) layer-1 recurrence + fused output projection
    gru_kernel<false><<<128, 128>>>(p_gi1, nullptr, mask, Whh_l1f, bhh_l1f, Whh_l1b, bhh_l1b,
                                    Wout, bout, out);
}

// round 13
// speedup vs baseline: 2.2822x; 1.0512x over previous
#include <cuda_runtime.h>

typedef unsigned long long ull;

#define Bb 256
#define Tt 512
#define Vv 30000
#define Ee 256

// ---------------- static device scratch ----------------
__device__ float g_embedW[(size_t)Vv * 192];       // [V][192] fwd 0..95, bwd 96..191 (bih folded, r/z pre-halved)
__device__ float g_x1[(size_t)Bb * Tt * 64];       // layer0 outputs [B][T][64]
__device__ float g_gi1[(size_t)Bb * Tt * 192];     // layer1 input gates (r/z pre-halved)

// ---------------- fast math ----------------
__device__ __forceinline__ float fast_tanh(float x) {
    float y; asm("tanh.approx.f32 %0, %1;" : "=f"(y) : "f"(x));
    return y;
}
__device__ __forceinline__ void fma2(ull& d, ull a, ull b) {
    asm("fma.rn.f32x2 %0, %1, %2, %0;" : "+l"(d) : "l"(a), "l"(b));
}
__device__ __forceinline__ ull add2(ull a, ull b) {
    ull r; asm("add.rn.f32x2 %0, %1, %2;" : "=l"(r) : "l"(a), "l"(b));
    return r;
}
__device__ __forceinline__ ull dup2(float v) {
    ull r; asm("mov.b64 %0, {%1, %1};" : "=l"(r) : "f"(v));
    return r;
}
__device__ __forceinline__ ull pack2(float lo, float hi) {
    ull r; asm("mov.b64 %0, {%1, %2};" : "=l"(r) : "f"(lo), "f"(hi));
    return r;
}
__device__ __forceinline__ float hsum2(ull v) {
    unsigned lo, hi;
    asm("mov.b64 {%0, %1}, %2;" : "=r"(lo), "=r"(hi) : "l"(v));
    return __uint_as_float(lo) + __uint_as_float(hi);
}

// ---------------- fused GEMM: C[M,192] = (A[M,K] @ [Wf;Wb]^T + bias) * colscale ----------------
// BM=64, BN=192, BK=16, 256 threads, single-buffer smem, 3 CTAs/SM.  (R6 proven config)
__global__ __launch_bounds__(256, 3)
void gemm192_kernel(const float* __restrict__ A,
                    const float* __restrict__ Wf, const float* __restrict__ Wb,
                    const float* __restrict__ bf, const float* __restrict__ bb_,
                    float* __restrict__ C, int M, int K,
                    const int* __restrict__ rowmask)
{
    __shared__ float As[16][68];
    __shared__ float Bs[16][196];

    int m0 = blockIdx.x * 64;
    if (rowmask && rowmask[m0] == 0) return;   // prefix mask: whole 64-row block padded

    int tid = threadIdx.x;
    int tx = tid & 31;        // cols tx + 32*j, j=0..5
    int ty = tid >> 5;        // rows ty*8 .. ty*8+7
    int lkk = tid & 15;
    int lrow = tid >> 4;

    const float* abase = A + (m0 + lrow) * K + lkk;
    const float* wfb = Wf + lrow * K + lkk;
    const float* wbb = Wb + lrow * K + lkk;
    bool arow_ok[4];
#pragma unroll
    for (int p = 0; p < 4; p++) arow_ok[p] = (m0 + lrow + 16 * p) < M;
    int K16 = K * 16;

    ull acc[4][6];
#pragma unroll
    for (int i = 0; i < 4; i++)
#pragma unroll
        for (int j = 0; j < 6; j++) acc[i][j] = 0ull;

    for (int k0 = 0; k0 < K; k0 += 16) {
#pragma unroll
        for (int p = 0; p < 4; p++)
            As[lkk][lrow + 16 * p] = arow_ok[p] ? abase[p * K16 + k0] : 0.f;
#pragma unroll
        for (int p = 0; p < 6; p++)
            Bs[lkk][lrow + 16 * p] = wfb[p * K16 + k0];
#pragma unroll
        for (int p = 6; p < 12; p++)
            Bs[lkk][lrow + 16 * p] = wbb[(p - 6) * K16 + k0];
        __syncthreads();
#pragma unroll
        for (int k = 0; k < 16; k++) {
            ulonglong2 q0 = *(const ulonglong2*)&As[k][ty * 8];
            ulonglong2 q1 = *(const ulonglong2*)&As[k][ty * 8 + 4];
            ull a2[4] = { q0.x, q0.y, q1.x, q1.y };
            ull b2[6];
#pragma unroll
            for (int j = 0; j < 6; j++) b2[j] = dup2(Bs[k][tx + 32 * j]);
#pragma unroll
            for (int i = 0; i < 4; i++)
#pragma unroll
                for (int j = 0; j < 6; j++)
                    fma2(acc[i][j], a2[i], b2[j]);
        }
        __syncthreads();
    }

#pragma unroll
    for (int j = 0; j < 6; j++) {
        int n = tx + 32 * j;
        // j: 0=r_f 1=z_f 2=n_f 3=r_b 4=z_b 5=n_b ; r/z pre-halved for tanh-form sigmoid
        float scale = (j == 2 || j == 5) ? 1.0f : 0.5f;
        float bias = (j < 3) ? bf[n] : bb_[n - 96];
#pragma unroll
        for (int i = 0; i < 4; i++) {
            int gm0 = m0 + ty * 8 + 2 * i;
            unsigned lo, hi;
            asm("mov.b64 {%0, %1}, %2;" : "=r"(lo), "=r"(hi) : "l"(acc[i][j]));
            if (gm0 < M)     C[(size_t)gm0 * 192 + n]       = (__uint_as_float(lo) + bias) * scale;
            if (gm0 + 1 < M) C[(size_t)(gm0 + 1) * 192 + n] = (__uint_as_float(hi) + bias) * scale;
        }
    }
}

// ---------------- GRU recurrence: warp = (batch, dir)  (R12 core + L2 prefetch for L1) ----------------
template<bool L0>
__global__ __launch_bounds__(128)
void gru_kernel(const float* __restrict__ gi,
                const int* __restrict__ ids,
                const int* __restrict__ mask,
                const float* __restrict__ Whh_f, const float* __restrict__ bhh_f,
                const float* __restrict__ Whh_b, const float* __restrict__ bhh_b,
                const float* __restrict__ Wout, const float* __restrict__ bout,
                float* __restrict__ out)
{
    __shared__ float sh[4][2][32];        // [warp][parity][lane]
    __shared__ int   sid[4][Tt];          // L0 only
    __shared__ float stop[2][64];         // L1 only: [pair-in-CTA][dir*32+lane]

    int wib = threadIdx.x >> 5;
    int lane = threadIdx.x & 31;
    int w = blockIdx.x * 4 + wib;
    int dir = w & 1;
    int b   = w >> 1;
    const float* Whh = dir ? Whh_b : Whh_f;
    const float* bhh = dir ? bhh_b : bhh_f;

    // Whh rows packed as f32x2 pairs; r/z rows pre-halved (tanh-form sigmoid)
    ull Wr2[16], Wz2[16], Wn2[16];
#pragma unroll
    for (int q = 0; q < 8; q++) {
        float4 v;
        v = *(const float4*)&Whh[lane * 32 + q * 4];
        Wr2[2*q]   = pack2(0.5f * v.x, 0.5f * v.y);
        Wr2[2*q+1] = pack2(0.5f * v.z, 0.5f * v.w);
        v = *(const float4*)&Whh[(32 + lane) * 32 + q * 4];
        Wz2[2*q]   = pack2(0.5f * v.x, 0.5f * v.y);
        Wz2[2*q+1] = pack2(0.5f * v.z, 0.5f * v.w);
        v = *(const float4*)&Whh[(64 + lane) * 32 + q * 4];
        Wn2[2*q]   = pack2(v.x, v.y);
        Wn2[2*q+1] = pack2(v.z, v.w);
    }
    ull bR = pack2(0.5f * bhh[lane], 0.f);
    ull bZ = pack2(0.5f * bhh[32 + lane], 0.f);
    ull bN = pack2(bhh[64 + lane], 0.f);

    // per-warp length from prefix mask (fused lens)
    int len = 0;
    {
        const int* mrow = mask + b * Tt;
#pragma unroll
        for (int i = 0; i < Tt / 32; i++) len += mrow[lane + 32 * i];
#pragma unroll
        for (int off = 16; off; off >>= 1) len += __shfl_xor_sync(0xffffffffu, len, off);
    }
    int lenm1 = len - 1;

    if (L0) {
        const int* idrow = ids + b * Tt;
        for (int i = lane; i < len; i += 32) sid[wib][i] = idrow[i];
        __syncwarp();
    }

    int tstep = dir ? -1 : 1;
    int tcur  = dir ? lenm1 : 0;

    // direction-adjusted base pointers
    const float* gi0  = gi + dir * 96;                              // L0: + sid[t]*192
    const float* gib  = gi + (size_t)b * Tt * 192 + dir * 96;       // L1: + t*192

    // clamped time index, branch-free
    auto tclamp = [&](int t) { return min(max(t, 0), lenm1); };
    auto gip = [&](int t) -> const float* {
        if (L0) return gi0 + (size_t)sid[wib][t] * 192;
        else    return gib + (size_t)t * 192;
    };

    // distance-3 prefetch pipeline (clamped -> no init branches)
    const float* p;
    p = gip(tclamp(tcur));
    float p0r = __ldg(p + lane), p0z = __ldg(p + 32 + lane), p0n = __ldg(p + 64 + lane);
    p = gip(tclamp(tcur + tstep));
    float p1r = __ldg(p + lane), p1z = __ldg(p + 32 + lane), p1n = __ldg(p + 64 + lane);
    p = gip(tclamp(tcur + 2 * tstep));
    float p2r = __ldg(p + lane), p2z = __ldg(p + 32 + lane), p2n = __ldg(p + 64 + lane);

    float h = 0.f;
    float* outp = L0 ? (g_x1 + ((size_t)b * Tt + tcur) * 64 + dir * 32 + lane) : nullptr;
    int outstep = tstep * 64;

#pragma unroll 6
    for (int s = 0; s < len; s++) {
        float cr = p0r, cz = p0z, cn = p0n;
        p0r = p1r; p0z = p1z; p0n = p1n;
        p1r = p2r; p1z = p2z; p1n = p2n;
        // branch-free clamped prefetch (redundant tail loads are harmless)
        p = gip(tclamp(tcur + 3 * tstep));
        p2r = __ldg(p + lane); p2z = __ldg(p + 32 + lane); p2n = __ldg(p + 64 + lane);

        if (!L0) {
            // gi1 misses L2 (DRAM, 577+ cyc): stage step t+8's lines into L2 early so
            // the distance-3 register pipeline only has to cover an L2 hit (~250 cyc).
            const float* pf = gib + (size_t)tclamp(tcur + 8 * tstep) * 192;
            asm volatile("prefetch.global.L2 [%0];" :: "l"(pf + lane));
            asm volatile("prefetch.global.L2 [%0];" :: "l"(pf + 32 + lane));
            asm volatile("prefetch.global.L2 [%0];" :: "l"(pf + 64 + lane));
        }

        int par = s & 1;
        sh[wib][par][lane] = h;
        __syncwarp();
        ull h2[16];
#pragma unroll
        for (int i = 0; i < 8; i++) {
            ulonglong2 q2 = *(const ulonglong2*)&sh[wib][par][4 * i];
            h2[2 * i] = q2.x; h2[2 * i + 1] = q2.y;
        }

        ull ra = bR, rb = 0ull, za = bZ, zb = 0ull, na = bN, nb2 = 0ull;
#pragma unroll
        for (int k = 0; k < 16; k += 2) {
            fma2(na,  Wn2[k],     h2[k]);
            fma2(nb2, Wn2[k + 1], h2[k + 1]);
            fma2(ra,  Wr2[k],     h2[k]);
            fma2(rb,  Wr2[k + 1], h2[k + 1]);
            fma2(za,  Wz2[k],     h2[k]);
            fma2(zb,  Wz2[k + 1], h2[k + 1]);
        }
        float ar = hsum2(add2(ra, rb));
        float az = hsum2(add2(za, zb));
        float an = hsum2(add2(na, nb2));

        // sigmoid(x) = 0.5 + 0.5*tanh(x/2); r/z args pre-halved upstream
        float r = fmaf(0.5f, fast_tanh(cr + ar), 0.5f);
        float z = fmaf(0.5f, fast_tanh(cz + az), 0.5f);
        float n = fast_tanh(fmaf(r, an, cn));
        h = fmaf(z, h - n, n);

        if (L0) { *outp = h; outp += outstep; }
        tcur += tstep;
    }

    if (!L0) {
        // fused output projection: warps (b,fwd) and (b,bwd) are CTA-adjacent
        int pi = wib >> 1;                       // batch pair index within CTA
        stop[pi][dir * 32 + lane] = h;
        __syncthreads();
        if (dir == 0) {
            float t0 = stop[pi][lane];
            float t1 = stop[pi][32 + lane];
#pragma unroll
            for (int o = 0; o < 6; o++) {
                float s2 = t0 * Wout[o * 64 + lane] + t1 * Wout[o * 64 + 32 + lane];
#pragma unroll
                for (int off = 16; off; off >>= 1) s2 += __shfl_xor_sync(0xffffffffu, s2, off);
                if (lane == 0) out[b * 6 + o] = s2 + bout[o];
            }
        }
    }
}

// ---------------- launch ----------------
extern "C" void kernel_launch(void* const* d_in, const int* in_sizes, int n_in,
                              void* d_out, int out_size)
{
    const int*   ids     = (const int*)d_in[0];
    const int*   mask    = (const int*)d_in[1];
    const float* embed   = (const float*)d_in[2];
    const float* Wih_l0f = (const float*)d_in[3];
    const float* Whh_l0f = (const float*)d_in[4];
    const float* bih_l0f = (const float*)d_in[5];
    const float* bhh_l0f = (const float*)d_in[6];
    const float* Wih_l0b = (const float*)d_in[7];
    const float* Whh_l0b = (const float*)d_in[8];
    const float* bih_l0b = (const float*)d_in[9];
    const float* bhh_l0b = (const float*)d_in[10];
    const float* Wih_l1f = (const float*)d_in[11];
    const float* Whh_l1f = (const float*)d_in[12];
    const float* bih_l1f = (const float*)d_in[13];
    const float* bhh_l1f = (const float*)d_in[14];
    const float* Wih_l1b = (const float*)d_in[15];
    const float* Whh_l1b = (const float*)d_in[16];
    const float* bih_l1b = (const float*)d_in[17];
    const float* bhh_l1b = (const float*)d_in[18];
    const float* Wout    = (const float*)d_in[19];
    const float* bout    = (const float*)d_in[20];
    float* out = (float*)d_out;

    float *p_embedW = nullptr, *p_x1 = nullptr, *p_gi1 = nullptr;
    cudaGetSymbolAddress((void**)&p_embedW, g_embedW);
    cudaGetSymbolAddress((void**)&p_x1, g_x1);
    cudaGetSymbolAddress((void**)&p_gi1, g_gi1);

    // 1) embedW = (embed @ [Wih_l0f;Wih_l0b]^T + bias) * colscale
    gemm192_kernel<<<(Vv + 63) / 64, 256>>>(embed, Wih_l0f, Wih_l0b, bih_l0f, bih_l0b,
                                            p_embedW, Vv, Ee, nullptr);
    // 2) layer-0 bidirectional recurrence -> x1  (lens fused per-warp)
    gru_kernel<true><<<128, 128>>>(p_embedW, ids, mask, Whh_l0f, bhh_l0f, Whh_l0b, bhh_l0b,
                                   nullptr, nullptr, nullptr);
    // 3) gi1 = (x1 @ [Wih_l1f;Wih_l1b]^T + bias) * colscale  (masked blocks skipped)
    gemm192_kernel<<<(Bb * Tt) / 64, 256>>>(p_x1, Wih_l1f, Wih_l1b, bih_l1f, bih_l1b,
                                            p_gi1, Bb * Tt, 64, mask);
    // 4) layer-1 recurrence + fused output projection (+ gi1 L2 prefetch)
    gru_kernel<false><<<128, 128>>>(p_gi1, nullptr, mask, Whh_l1f, bhh_l1f, Whh_l1b, bhh_l1b,
                                    Wout, bout, out);
}

// round 14
// speedup vs baseline: 2.2827x; 1.0002x over previous
#include <cuda_runtime.h>

typedef unsigned long long ull;

#define Bb 256
#define Tt 512
#define Vv 30000
#define Ee 256

// ---------------- static device scratch ----------------
__device__ float g_embedW[(size_t)Vv * 192];       // [V][192] fwd 0..95, bwd 96..191 (bih folded, r/z pre-halved)
__device__ float g_x1[(size_t)Bb * Tt * 64];       // layer0 outputs [B][T][64]
__device__ float g_gi1[(size_t)Bb * Tt * 192];     // layer1 input gates (r/z pre-halved)

// ---------------- fast math ----------------
__device__ __forceinline__ float fast_tanh(float x) {
    float y; asm("tanh.approx.f32 %0, %1;" : "=f"(y) : "f"(x));
    return y;
}
__device__ __forceinline__ void fma2(ull& d, ull a, ull b) {
    asm("fma.rn.f32x2 %0, %1, %2, %0;" : "+l"(d) : "l"(a), "l"(b));
}
__device__ __forceinline__ ull add2(ull a, ull b) {
    ull r; asm("add.rn.f32x2 %0, %1, %2;" : "=l"(r) : "l"(a), "l"(b));
    return r;
}
__device__ __forceinline__ ull dup2(float v) {
    ull r; asm("mov.b64 %0, {%1, %1};" : "=l"(r) : "f"(v));
    return r;
}
__device__ __forceinline__ ull pack2(float lo, float hi) {
    ull r; asm("mov.b64 %0, {%1, %2};" : "=l"(r) : "f"(lo), "f"(hi));
    return r;
}
__device__ __forceinline__ float hsum2(ull v) {
    unsigned lo, hi;
    asm("mov.b64 {%0, %1}, %2;" : "=r"(lo), "=r"(hi) : "l"(v));
    return __uint_as_float(lo) + __uint_as_float(hi);
}

// ---------------- fused GEMM: C[M,192] = (A[M,K] @ [Wf;Wb]^T + bias) * colscale ----------------
// BM=64, BN=192, BK=16, 256 threads, single-buffer smem, 3 CTAs/SM.  (R6 proven config)
__global__ __launch_bounds__(256, 3)
void gemm192_kernel(const float* __restrict__ A,
                    const float* __restrict__ Wf, const float* __restrict__ Wb,
                    const float* __restrict__ bf, const float* __restrict__ bb_,
                    float* __restrict__ C, int M, int K,
                    const int* __restrict__ rowmask)
{
    __shared__ float As[16][68];
    __shared__ float Bs[16][196];

    int m0 = blockIdx.x * 64;
    if (rowmask && rowmask[m0] == 0) return;   // prefix mask: whole 64-row block padded

    int tid = threadIdx.x;
    int tx = tid & 31;        // cols tx + 32*j, j=0..5
    int ty = tid >> 5;        // rows ty*8 .. ty*8+7
    int lkk = tid & 15;
    int lrow = tid >> 4;

    const float* abase = A + (m0 + lrow) * K + lkk;
    const float* wfb = Wf + lrow * K + lkk;
    const float* wbb = Wb + lrow * K + lkk;
    bool arow_ok[4];
#pragma unroll
    for (int p = 0; p < 4; p++) arow_ok[p] = (m0 + lrow + 16 * p) < M;
    int K16 = K * 16;

    ull acc[4][6];
#pragma unroll
    for (int i = 0; i < 4; i++)
#pragma unroll
        for (int j = 0; j < 6; j++) acc[i][j] = 0ull;

    for (int k0 = 0; k0 < K; k0 += 16) {
#pragma unroll
        for (int p = 0; p < 4; p++)
            As[lkk][lrow + 16 * p] = arow_ok[p] ? abase[p * K16 + k0] : 0.f;
#pragma unroll
        for (int p = 0; p < 6; p++)
            Bs[lkk][lrow + 16 * p] = wfb[p * K16 + k0];
#pragma unroll
        for (int p = 6; p < 12; p++)
            Bs[lkk][lrow + 16 * p] = wbb[(p - 6) * K16 + k0];
        __syncthreads();
#pragma unroll
        for (int k = 0; k < 16; k++) {
            ulonglong2 q0 = *(const ulonglong2*)&As[k][ty * 8];
            ulonglong2 q1 = *(const ulonglong2*)&As[k][ty * 8 + 4];
            ull a2[4] = { q0.x, q0.y, q1.x, q1.y };
            ull b2[6];
#pragma unroll
            for (int j = 0; j < 6; j++) b2[j] = dup2(Bs[k][tx + 32 * j]);
#pragma unroll
            for (int i = 0; i < 4; i++)
#pragma unroll
                for (int j = 0; j < 6; j++)
                    fma2(acc[i][j], a2[i], b2[j]);
        }
        __syncthreads();
    }

#pragma unroll
    for (int j = 0; j < 6; j++) {
        int n = tx + 32 * j;
        // j: 0=r_f 1=z_f 2=n_f 3=r_b 4=z_b 5=n_b ; r/z pre-halved for tanh-form sigmoid
        float scale = (j == 2 || j == 5) ? 1.0f : 0.5f;
        float bias = (j < 3) ? bf[n] : bb_[n - 96];
#pragma unroll
        for (int i = 0; i < 4; i++) {
            int gm0 = m0 + ty * 8 + 2 * i;
            unsigned lo, hi;
            asm("mov.b64 {%0, %1}, %2;" : "=r"(lo), "=r"(hi) : "l"(acc[i][j]));
            if (gm0 < M)     C[(size_t)gm0 * 192 + n]       = (__uint_as_float(lo) + bias) * scale;
            if (gm0 + 1 < M) C[(size_t)(gm0 + 1) * 192 + n] = (__uint_as_float(hi) + bias) * scale;
        }
    }
}

// ---------------- GRU recurrence: warp = (batch, dir) ----------------
// PD = register prefetch pipeline depth: 3 for L0 (embedW L2-resident),
// 6 for L1 (gi1 comes from DRAM; 6*step ~ 1500 cyc lead >> 577 cyc DRAM).
template<bool L0, int PD>
__global__ __launch_bounds__(128)
void gru_kernel(const float* __restrict__ gi,
                const int* __restrict__ ids,
                const int* __restrict__ mask,
                const float* __restrict__ Whh_f, const float* __restrict__ bhh_f,
                const float* __restrict__ Whh_b, const float* __restrict__ bhh_b,
                const float* __restrict__ Wout, const float* __restrict__ bout,
                float* __restrict__ out)
{
    __shared__ float sh[4][2][32];        // [warp][parity][lane]
    __shared__ int   sid[4][Tt];          // L0 only
    __shared__ float stop[2][64];         // L1 only: [pair-in-CTA][dir*32+lane]

    int wib = threadIdx.x >> 5;
    int lane = threadIdx.x & 31;
    int w = blockIdx.x * 4 + wib;
    int dir = w & 1;
    int b   = w >> 1;
    const float* Whh = dir ? Whh_b : Whh_f;
    const float* bhh = dir ? bhh_b : bhh_f;

    // Whh rows packed as f32x2 pairs; r/z rows pre-halved (tanh-form sigmoid)
    ull Wr2[16], Wz2[16], Wn2[16];
#pragma unroll
    for (int q = 0; q < 8; q++) {
        float4 v;
        v = *(const float4*)&Whh[lane * 32 + q * 4];
        Wr2[2*q]   = pack2(0.5f * v.x, 0.5f * v.y);
        Wr2[2*q+1] = pack2(0.5f * v.z, 0.5f * v.w);
        v = *(const float4*)&Whh[(32 + lane) * 32 + q * 4];
        Wz2[2*q]   = pack2(0.5f * v.x, 0.5f * v.y);
        Wz2[2*q+1] = pack2(0.5f * v.z, 0.5f * v.w);
        v = *(const float4*)&Whh[(64 + lane) * 32 + q * 4];
        Wn2[2*q]   = pack2(v.x, v.y);
        Wn2[2*q+1] = pack2(v.z, v.w);
    }
    ull bR = pack2(0.5f * bhh[lane], 0.f);
    ull bZ = pack2(0.5f * bhh[32 + lane], 0.f);
    ull bN = pack2(bhh[64 + lane], 0.f);

    // per-warp length from prefix mask (fused lens)
    int len = 0;
    {
        const int* mrow = mask + b * Tt;
#pragma unroll
        for (int i = 0; i < Tt / 32; i++) len += mrow[lane + 32 * i];
#pragma unroll
        for (int off = 16; off; off >>= 1) len += __shfl_xor_sync(0xffffffffu, len, off);
    }
    int lenm1 = len - 1;

    if (L0) {
        const int* idrow = ids + b * Tt;
        for (int i = lane; i < len; i += 32) sid[wib][i] = idrow[i];
        __syncwarp();
    }

    int tstep = dir ? -1 : 1;
    int tcur  = dir ? lenm1 : 0;

    // direction-adjusted base pointers
    const float* gi0  = gi + dir * 96;                              // L0: + sid[t]*192
    const float* gib  = gi + (size_t)b * Tt * 192 + dir * 96;       // L1: + t*192

    // clamped time index, branch-free
    auto tclamp = [&](int t) { return min(max(t, 0), lenm1); };
    auto gip = [&](int t) -> const float* {
        if (L0) return gi0 + (size_t)sid[wib][t] * 192;
        else    return gib + (size_t)t * 192;
    };

    // distance-PD register prefetch pipeline (clamped -> no init branches)
    float pr[PD], pz[PD], pn[PD];
#pragma unroll
    for (int d = 0; d < PD; d++) {
        const float* p = gip(tclamp(tcur + d * tstep));
        pr[d] = __ldg(p + lane); pz[d] = __ldg(p + 32 + lane); pn[d] = __ldg(p + 64 + lane);
    }

    float h = 0.f;
    float* outp = L0 ? (g_x1 + ((size_t)b * Tt + tcur) * 64 + dir * 32 + lane) : nullptr;
    int outstep = tstep * 64;

#pragma unroll 6
    for (int s = 0; s < len; s++) {
        float cr = pr[0], cz = pz[0], cn = pn[0];
#pragma unroll
        for (int d = 0; d < PD - 1; d++) {
            pr[d] = pr[d + 1]; pz[d] = pz[d + 1]; pn[d] = pn[d + 1];
        }
        // branch-free clamped prefetch (redundant tail loads are harmless)
        const float* p = gip(tclamp(tcur + PD * tstep));
        pr[PD - 1] = __ldg(p + lane);
        pz[PD - 1] = __ldg(p + 32 + lane);
        pn[PD - 1] = __ldg(p + 64 + lane);

        int par = s & 1;
        sh[wib][par][lane] = h;
        __syncwarp();
        ull h2[16];
#pragma unroll
        for (int i = 0; i < 8; i++) {
            ulonglong2 q2 = *(const ulonglong2*)&sh[wib][par][4 * i];
            h2[2 * i] = q2.x; h2[2 * i + 1] = q2.y;
        }

        ull ra = bR, rb = 0ull, za = bZ, zb = 0ull, na = bN, nb2 = 0ull;
#pragma unroll
        for (int k = 0; k < 16; k += 2) {
            fma2(na,  Wn2[k],     h2[k]);
            fma2(nb2, Wn2[k + 1], h2[k + 1]);
            fma2(ra,  Wr2[k],     h2[k]);
            fma2(rb,  Wr2[k + 1], h2[k + 1]);
            fma2(za,  Wz2[k],     h2[k]);
            fma2(zb,  Wz2[k + 1], h2[k + 1]);
        }
        float ar = hsum2(add2(ra, rb));
        float az = hsum2(add2(za, zb));
        float an = hsum2(add2(na, nb2));

        // sigmoid(x) = 0.5 + 0.5*tanh(x/2); r/z args pre-halved upstream
        float r = fmaf(0.5f, fast_tanh(cr + ar), 0.5f);
        float z = fmaf(0.5f, fast_tanh(cz + az), 0.5f);
        float n = fast_tanh(fmaf(r, an, cn));
        h = fmaf(z, h - n, n);

        if (L0) { *outp = h; outp += outstep; }
        tcur += tstep;
    }

    if (!L0) {
        // fused output projection: warps (b,fwd) and (b,bwd) are CTA-adjacent
        int pi = wib >> 1;                       // batch pair index within CTA
        stop[pi][dir * 32 + lane] = h;
        __syncthreads();
        if (dir == 0) {
            float t0 = stop[pi][lane];
            float t1 = stop[pi][32 + lane];
#pragma unroll
            for (int o = 0; o < 6; o++) {
                float s2 = t0 * Wout[o * 64 + lane] + t1 * Wout[o * 64 + 32 + lane];
#pragma unroll
                for (int off = 16; off; off >>= 1) s2 += __shfl_xor_sync(0xffffffffu, s2, off);
                if (lane == 0) out[b * 6 + o] = s2 + bout[o];
            }
        }
    }
}

// ---------------- launch ----------------
extern "C" void kernel_launch(void* const* d_in, const int* in_sizes, int n_in,
                              void* d_out, int out_size)
{
    const int*   ids     = (const int*)d_in[0];
    const int*   mask    = (const int*)d_in[1];
    const float* embed   = (const float*)d_in[2];
    const float* Wih_l0f = (const float*)d_in[3];
    const float* Whh_l0f = (const float*)d_in[4];
    const float* bih_l0f = (const float*)d_in[5];
    const float* bhh_l0f = (const float*)d_in[6];
    const float* Wih_l0b = (const float*)d_in[7];
    const float* Whh_l0b = (const float*)d_in[8];
    const float* bih_l0b = (const float*)d_in[9];
    const float* bhh_l0b = (const float*)d_in[10];
    const float* Wih_l1f = (const float*)d_in[11];
    const float* Whh_l1f = (const float*)d_in[12];
    const float* bih_l1f = (const float*)d_in[13];
    const float* bhh_l1f = (const float*)d_in[14];
    const float* Wih_l1b = (const float*)d_in[15];
    const float* Whh_l1b = (const float*)d_in[16];
    const float* bih_l1b = (const float*)d_in[17];
    const float* bhh_l1b = (const float*)d_in[18];
    const float* Wout    = (const float*)d_in[19];
    const float* bout    = (const float*)d_in[20];
    float* out = (float*)d_out;

    float *p_embedW = nullptr, *p_x1 = nullptr, *p_gi1 = nullptr;
    cudaGetSymbolAddress((void**)&p_embedW, g_embedW);
    cudaGetSymbolAddress((void**)&p_x1, g_x1);
    cudaGetSymbolAddress((void**)&p_gi1, g_gi1);

    // 1) embedW = (embed @ [Wih_l0f;Wih_l0b]^T + bias) * colscale
    gemm192_kernel<<<(Vv + 63) / 64, 256>>>(embed, Wih_l0f, Wih_l0b, bih_l0f, bih_l0b,
                                            p_embedW, Vv, Ee, nullptr);
    // 2) layer-0 bidirectional recurrence -> x1  (depth-3 pipeline; embedW is L2-resident)
    gru_kernel<true, 3><<<128, 128>>>(p_embedW, ids, mask, Whh_l0f, bhh_l0f, Whh_l0b, bhh_l0b,
                                      nullptr, nullptr, nullptr);
    // 3) gi1 = (x1 @ [Wih_l1f;Wih_l1b]^T + bias) * colscale  (masked blocks skipped)
    gemm192_kernel<<<(Bb * Tt) / 64, 256>>>(p_x1, Wih_l1f, Wih_l1b, bih_l1f, bih_l1b,
                                            p_gi1, Bb * Tt, 64, mask);
    // 4) layer-1 recurrence + fused output projection  (depth-6 pipeline covers DRAM directly)
    gru_kernel<false, 6><<<128, 128>>>(p_gi1, nullptr, mask, Whh_l1f, bhh_l1f, Whh_l1b, bhh_l1b,
                                       Wout, bout, out);
}

// round 16
// speedup vs baseline: 2.2877x; 1.0022x over previous
#include <cuda_runtime.h>

typedef unsigned long long ull;

#define Bb 256
#define Tt 512
#define Vv 30000
#define Ee 256

// ---------------- static device scratch ----------------
__device__ float g_embedW[(size_t)Vv * 192];       // [V][192] fwd 0..95, bwd 96..191 (bih folded, r/z pre-halved)
__device__ float g_x1[(size_t)Bb * Tt * 64];       // layer0 outputs [B][T][64]
__device__ float g_gi1[(size_t)Bb * Tt * 192];     // layer1 input gates (r/z pre-halved)

// ---------------- fast math ----------------
__device__ __forceinline__ float fast_tanh(float x) {
    float y; asm("tanh.approx.f32 %0, %1;" : "=f"(y) : "f"(x));
    return y;
}
__device__ __forceinline__ void fma2(ull& d, ull a, ull b) {
    asm("fma.rn.f32x2 %0, %1, %2, %0;" : "+l"(d) : "l"(a), "l"(b));
}
__device__ __forceinline__ ull add2(ull a, ull b) {
    ull r; asm("add.rn.f32x2 %0, %1, %2;" : "=l"(r) : "l"(a), "l"(b));
    return r;
}
__device__ __forceinline__ ull dup2(float v) {
    ull r; asm("mov.b64 %0, {%1, %1};" : "=l"(r) : "f"(v));
    return r;
}
__device__ __forceinline__ ull pack2(float lo, float hi) {
    ull r; asm("mov.b64 %0, {%1, %2};" : "=l"(r) : "f"(lo), "f"(hi));
    return r;
}
__device__ __forceinline__ float hsum2(ull v) {
    unsigned lo, hi;
    asm("mov.b64 {%0, %1}, %2;" : "=r"(lo), "=r"(hi) : "l"(v));
    return __uint_as_float(lo) + __uint_as_float(hi);
}
// L2 cache policies (createpolicy + cache_hint form: legal for scalar ld/st on sm_103)
__device__ __forceinline__ ull policy_evict_last() {
    ull p; asm("createpolicy.fractional.L2::evict_last.b64 %0, 1.0;" : "=l"(p));
    return p;
}
__device__ __forceinline__ ull policy_evict_first() {
    ull p; asm("createpolicy.fractional.L2::evict_first.b64 %0, 1.0;" : "=l"(p));
    return p;
}
__device__ __forceinline__ float ldg_hint(const float* p, ull pol) {
    float v; asm("ld.global.L2::cache_hint.f32 %0, [%1], %2;" : "=f"(v) : "l"(p), "l"(pol));
    return v;
}
__device__ __forceinline__ void stg_hint(float* p, float v, ull pol) {
    asm volatile("st.global.L2::cache_hint.f32 [%0], %1, %2;" :: "l"(p), "f"(v), "l"(pol) : "memory");
}

// ---------------- fused GEMM: C[M,192] = (A[M,K] @ [Wf;Wb]^T + bias) * colscale ----------------
// BM=64, BN=192, BK=16, 256 threads, single-buffer smem, 3 CTAs/SM.  (R6 proven config)
// A reads evict_first (streamed once); C writes evict_last (read back by the GRU kernel).
__global__ __launch_bounds__(256, 3)
void gemm192_kernel(const float* __restrict__ A,
                    const float* __restrict__ Wf, const float* __restrict__ Wb,
                    const float* __restrict__ bf, const float* __restrict__ bb_,
                    float* __restrict__ C, int M, int K,
                    const int* __restrict__ rowmask)
{
    __shared__ float As[16][68];
    __shared__ float Bs[16][196];

    int m0 = blockIdx.x * 64;
    if (rowmask && rowmask[m0] == 0) return;   // prefix mask: whole 64-row block padded

    int tid = threadIdx.x;
    int tx = tid & 31;        // cols tx + 32*j, j=0..5
    int ty = tid >> 5;        // rows ty*8 .. ty*8+7
    int lkk = tid & 15;
    int lrow = tid >> 4;

    ull pol_ef = policy_evict_first();
    ull pol_el = policy_evict_last();

    const float* abase = A + (m0 + lrow) * K + lkk;
    const float* wfb = Wf + lrow * K + lkk;
    const float* wbb = Wb + lrow * K + lkk;
    bool arow_ok[4];
#pragma unroll
    for (int p = 0; p < 4; p++) arow_ok[p] = (m0 + lrow + 16 * p) < M;
    int K16 = K * 16;

    ull acc[4][6];
#pragma unroll
    for (int i = 0; i < 4; i++)
#pragma unroll
        for (int j = 0; j < 6; j++) acc[i][j] = 0ull;

    for (int k0 = 0; k0 < K; k0 += 16) {
#pragma unroll
        for (int p = 0; p < 4; p++)
            As[lkk][lrow + 16 * p] = arow_ok[p] ? ldg_hint(abase + p * K16 + k0, pol_ef) : 0.f;
#pragma unroll
        for (int p = 0; p < 6; p++)
            Bs[lkk][lrow + 16 * p] = wfb[p * K16 + k0];
#pragma unroll
        for (int p = 6; p < 12; p++)
            Bs[lkk][lrow + 16 * p] = wbb[(p - 6) * K16 + k0];
        __syncthreads();
#pragma unroll
        for (int k = 0; k < 16; k++) {
            ulonglong2 q0 = *(const ulonglong2*)&As[k][ty * 8];
            ulonglong2 q1 = *(const ulonglong2*)&As[k][ty * 8 + 4];
            ull a2[4] = { q0.x, q0.y, q1.x, q1.y };
            ull b2[6];
#pragma unroll
            for (int j = 0; j < 6; j++) b2[j] = dup2(Bs[k][tx + 32 * j]);
#pragma unroll
            for (int i = 0; i < 4; i++)
#pragma unroll
                for (int j = 0; j < 6; j++)
                    fma2(acc[i][j], a2[i], b2[j]);
        }
        __syncthreads();
    }

#pragma unroll
    for (int j = 0; j < 6; j++) {
        int n = tx + 32 * j;
        // j: 0=r_f 1=z_f 2=n_f 3=r_b 4=z_b 5=n_b ; r/z pre-halved for tanh-form sigmoid
        float scale = (j == 2 || j == 5) ? 1.0f : 0.5f;
        float bias = (j < 3) ? bf[n] : bb_[n - 96];
#pragma unroll
        for (int i = 0; i < 4; i++) {
            int gm0 = m0 + ty * 8 + 2 * i;
            unsigned lo, hi;
            asm("mov.b64 {%0, %1}, %2;" : "=r"(lo), "=r"(hi) : "l"(acc[i][j]));
            if (gm0 < M)     stg_hint(C + (size_t)gm0 * 192 + n,       (__uint_as_float(lo) + bias) * scale, pol_el);
            if (gm0 + 1 < M) stg_hint(C + (size_t)(gm0 + 1) * 192 + n, (__uint_as_float(hi) + bias) * scale, pol_el);
        }
    }
}

// ---------------- GRU recurrence: warp = (batch, dir)  (R13 proven form) ----------------
template<bool L0>
__global__ __launch_bounds__(128)
void gru_kernel(const float* __restrict__ gi,
                const int* __restrict__ ids,
                const int* __restrict__ mask,
                const float* __restrict__ Whh_f, const float* __restrict__ bhh_f,
                const float* __restrict__ Whh_b, const float* __restrict__ bhh_b,
                const float* __restrict__ Wout, const float* __restrict__ bout,
                float* __restrict__ out)
{
    __shared__ float sh[4][2][32];        // [warp][parity][lane]
    __shared__ int   sid[4][Tt];          // L0 only
    __shared__ float stop[2][64];         // L1 only: [pair-in-CTA][dir*32+lane]

    int wib = threadIdx.x >> 5;
    int lane = threadIdx.x & 31;
    int w = blockIdx.x * 4 + wib;
    int dir = w & 1;
    int b   = w >> 1;
    const float* Whh = dir ? Whh_b : Whh_f;
    const float* bhh = dir ? bhh_b : bhh_f;

    // Whh rows packed as f32x2 pairs; r/z rows pre-halved (tanh-form sigmoid)
    ull Wr2[16], Wz2[16], Wn2[16];
#pragma unroll
    for (int q = 0; q < 8; q++) {
        float4 v;
        v = *(const float4*)&Whh[lane * 32 + q * 4];
        Wr2[2*q]   = pack2(0.5f * v.x, 0.5f * v.y);
        Wr2[2*q+1] = pack2(0.5f * v.z, 0.5f * v.w);
        v = *(const float4*)&Whh[(32 + lane) * 32 + q * 4];
        Wz2[2*q]   = pack2(0.5f * v.x, 0.5f * v.y);
        Wz2[2*q+1] = pack2(0.5f * v.z, 0.5f * v.w);
        v = *(const float4*)&Whh[(64 + lane) * 32 + q * 4];
        Wn2[2*q]   = pack2(v.x, v.y);
        Wn2[2*q+1] = pack2(v.z, v.w);
    }
    ull bR = pack2(0.5f * bhh[lane], 0.f);
    ull bZ = pack2(0.5f * bhh[32 + lane], 0.f);
    ull bN = pack2(bhh[64 + lane], 0.f);

    // per-warp length from prefix mask (fused lens)
    int len = 0;
    {
        const int* mrow = mask + b * Tt;
#pragma unroll
        for (int i = 0; i < Tt / 32; i++) len += mrow[lane + 32 * i];
#pragma unroll
        for (int off = 16; off; off >>= 1) len += __shfl_xor_sync(0xffffffffu, len, off);
    }
    int lenm1 = len - 1;

    if (L0) {
        const int* idrow = ids + b * Tt;
        for (int i = lane; i < len; i += 32) sid[wib][i] = idrow[i];
        __syncwarp();
    }

    int tstep = dir ? -1 : 1;
    int tcur  = dir ? lenm1 : 0;

    // direction-adjusted base pointers
    const float* gi0  = gi + dir * 96;                              // L0: + sid[t]*192
    const float* gib  = gi + (size_t)b * Tt * 192 + dir * 96;       // L1: + t*192

    // clamped time index, branch-free
    auto tclamp = [&](int t) { return min(max(t, 0), lenm1); };
    auto gip = [&](int t) -> const float* {
        if (L0) return gi0 + (size_t)sid[wib][t] * 192;
        else    return gib + (size_t)t * 192;
    };

    // distance-3 prefetch pipeline (clamped -> no init branches)
    const float* p;
    p = gip(tclamp(tcur));
    float p0r = __ldg(p + lane), p0z = __ldg(p + 32 + lane), p0n = __ldg(p + 64 + lane);
    p = gip(tclamp(tcur + tstep));
    float p1r = __ldg(p + lane), p1z = __ldg(p + 32 + lane), p1n = __ldg(p + 64 + lane);
    p = gip(tclamp(tcur + 2 * tstep));
    float p2r = __ldg(p + lane), p2z = __ldg(p + 32 + lane), p2n = __ldg(p + 64 + lane);

    float h = 0.f;
    float* outp = L0 ? (g_x1 + ((size_t)b * Tt + tcur) * 64 + dir * 32 + lane) : nullptr;
    int outstep = tstep * 64;

#pragma unroll 6
    for (int s = 0; s < len; s++) {
        float cr = p0r, cz = p0z, cn = p0n;
        p0r = p1r; p0z = p1z; p0n = p1n;
        p1r = p2r; p1z = p2z; p1n = p2n;
        // branch-free clamped prefetch (redundant tail loads are harmless)
        p = gip(tclamp(tcur + 3 * tstep));
        p2r = __ldg(p + lane); p2z = __ldg(p + 32 + lane); p2n = __ldg(p + 64 + lane);

        if (!L0) {
            // backstop: stage step t+8's lines into L2 (covers anything the
            // evict_last GEMM writes didn't keep resident).
            const float* pf = gib + (size_t)tclamp(tcur + 8 * tstep) * 192;
            asm volatile("prefetch.global.L2 [%0];" :: "l"(pf + lane));
            asm volatile("prefetch.global.L2 [%0];" :: "l"(pf + 32 + lane));
            asm volatile("prefetch.global.L2 [%0];" :: "l"(pf + 64 + lane));
        }

        int par = s & 1;
        sh[wib][par][lane] = h;
        __syncwarp();
        ull h2[16];
#pragma unroll
        for (int i = 0; i < 8; i++) {
            ulonglong2 q2 = *(const ulonglong2*)&sh[wib][par][4 * i];
            h2[2 * i] = q2.x; h2[2 * i + 1] = q2.y;
        }

        ull ra = bR, rb = 0ull, za = bZ, zb = 0ull, na = bN, nb2 = 0ull;
#pragma unroll
        for (int k = 0; k < 16; k += 2) {
            fma2(na,  Wn2[k],     h2[k]);
            fma2(nb2, Wn2[k + 1], h2[k + 1]);
            fma2(ra,  Wr2[k],     h2[k]);
            fma2(rb,  Wr2[k + 1], h2[k + 1]);
            fma2(za,  Wz2[k],     h2[k]);
            fma2(zb,  Wz2[k + 1], h2[k + 1]);
        }
        float ar = hsum2(add2(ra, rb));
        float az = hsum2(add2(za, zb));
        float an = hsum2(add2(na, nb2));

        // sigmoid(x) = 0.5 + 0.5*tanh(x/2); r/z args pre-halved upstream
        float r = fmaf(0.5f, fast_tanh(cr + ar), 0.5f);
        float z = fmaf(0.5f, fast_tanh(cz + az), 0.5f);
        float n = fast_tanh(fmaf(r, an, cn));
        h = fmaf(z, h - n, n);

        if (L0) { *outp = h; outp += outstep; }
        tcur += tstep;
    }

    if (!L0) {
        // fused output projection: warps (b,fwd) and (b,bwd) are CTA-adjacent
        int pi = wib >> 1;                       // batch pair index within CTA
        stop[pi][dir * 32 + lane] = h;
        __syncthreads();
        if (dir == 0) {
            float t0 = stop[pi][lane];
            float t1 = stop[pi][32 + lane];
#pragma unroll
            for (int o = 0; o < 6; o++) {
                float s2 = t0 * Wout[o * 64 + lane] + t1 * Wout[o * 64 + 32 + lane];
#pragma unroll
                for (int off = 16; off; off >>= 1) s2 += __shfl_xor_sync(0xffffffffu, s2, off);
                if (lane == 0) out[b * 6 + o] = s2 + bout[o];
            }
        }
    }
}

// ---------------- launch ----------------
extern "C" void kernel_launch(void* const* d_in, const int* in_sizes, int n_in,
                              void* d_out, int out_size)
{
    const int*   ids     = (const int*)d_in[0];
    const int*   mask    = (const int*)d_in[1];
    const float* embed   = (const float*)d_in[2];
    const float* Wih_l0f = (const float*)d_in[3];
    const float* Whh_l0f = (const float*)d_in[4];
    const float* bih_l0f = (const float*)d_in[5];
    const float* bhh_l0f = (const float*)d_in[6];
    const float* Wih_l0b = (const float*)d_in[7];
    const float* Whh_l0b = (const float*)d_in[8];
    const float* bih_l0b = (const float*)d_in[9];
    const float* bhh_l0b = (const float*)d_in[10];
    const float* Wih_l1f = (const float*)d_in[11];
    const float* Whh_l1f = (const float*)d_in[12];
    const float* bih_l1f = (const float*)d_in[13];
    const float* bhh_l1f = (const float*)d_in[14];
    const float* Wih_l1b = (const float*)d_in[15];
    const float* Whh_l1b = (const float*)d_in[16];
    const float* bih_l1b = (const float*)d_in[17];
    const float* bhh_l1b = (const float*)d_in[18];
    const float* Wout    = (const float*)d_in[19];
    const float* bout    = (const float*)d_in[20];
    float* out = (float*)d_out;

    float *p_embedW = nullptr, *p_x1 = nullptr, *p_gi1 = nullptr;
    cudaGetSymbolAddress((void**)&p_embedW, g_embedW);
    cudaGetSymbolAddress((void**)&p_x1, g_x1);
    cudaGetSymbolAddress((void**)&p_gi1, g_gi1);

    // 1) embedW = (embed @ [Wih_l0f;Wih_l0b]^T + bias) * colscale   (output pinned in L2)
    gemm192_kernel<<<(Vv + 63) / 64, 256>>>(embed, Wih_l0f, Wih_l0b, bih_l0f, bih_l0b,
                                            p_embedW, Vv, Ee, nullptr);
    // 2) layer-0 bidirectional recurrence -> x1  (lens fused per-warp)
    gru_kernel<true><<<128, 128>>>(p_embedW, ids, mask, Whh_l0f, bhh_l0f, Whh_l0b, bhh_l0b,
                                   nullptr, nullptr, nullptr);
    // 3) gi1 = (x1 @ [Wih_l1f;Wih_l1b]^T + bias) * colscale  (masked blocks skipped; output pinned)
    gemm192_kernel<<<(Bb * Tt) / 64, 256>>>(p_x1, Wih_l1f, Wih_l1b, bih_l1f, bih_l1b,
                                            p_gi1, Bb * Tt, 64, mask);
    // 4) layer-1 recurrence + fused output projection (+ gi1 L2 prefetch backstop)
    gru_kernel<false><<<128, 128>>>(p_gi1, nullptr, mask, Whh_l1f, bhh_l1f, Whh_l1b, bhh_l1b,
                                    Wout, bout, out);
}